// round 1
// baseline (speedup 1.0000x reference)
#include <cuda_runtime.h>
#include <math.h>
#include <stdint.h>
#include <stddef.h>

// ---------------- problem constants ----------------
#define NSEQ 8
#define SSEQ 448
#define DMODEL 768
#define MAXT 3584          // >= N*(S-1) = 3576
#define MAXVB 782          // ceil(50000/64)

// ---------------- device scratch (no allocs allowed) ----------------
__device__ float g_X[MAXT * DMODEL];          // gathered predictor states  [T,768]
__device__ float g_H[MAXT * 256];             // head-transform output (row stride = Dh of current head)
__device__ float g_pm[MAXVB * MAXT];          // partial max     [nVB, T]
__device__ float g_ps[MAXVB * MAXT];          // partial sumexp  [nVB, T]
__device__ float g_psl[MAXVB * MAXT];         // partial sum-logits
__device__ float g_acc[16];                   // loss accumulators

// ---------------- small kernels ----------------
__global__ void zero_acc_k() {
    if (threadIdx.x < 16) g_acc[threadIdx.x] = 0.0f;
}

// x[i,:] = tr_hidden[s, n, :] with hsel[i] = n*S + s  (flat = transpose(S,N,D)->(N*S,D))
__global__ void gather_x_k(const float* __restrict__ hid, const int* __restrict__ hsel) {
    int i = blockIdx.x;
    int idx = hsel[i];
    int s = idx % SSEQ;
    int n = idx / SSEQ;
    const float4* src = (const float4*)(hid + ((size_t)s * NSEQ + n) * DMODEL);
    float4* dst = (float4*)(g_X + (size_t)i * DMODEL);
    dst[threadIdx.x] = src[threadIdx.x];   // 192 threads * float4 = 768 floats
}

// ---------------- GEMM 1: H = gelu(X @ W + b), W is [768, Dh] row-major ----------------
// Tiling: BM=BN=64, BK=16, 256 threads, 4x4 microtile. Optional row indirection for A (affix head).
__global__ void gemm_nn_gelu_k(const float* __restrict__ W, const float* __restrict__ bias,
                               const int* __restrict__ rowidx, int M, int Nn) {
    __shared__ __align__(16) float As[16][68];
    __shared__ __align__(16) float Bs[16][68];
    int m0 = blockIdx.y * 64, n0 = blockIdx.x * 64;
    int tid = threadIdx.x;
    int tx = tid & 15, ty = tid >> 4;
    int lrow = tid >> 2, lk4 = (tid & 3) * 4;     // A-loader mapping
    int lkb  = tid >> 4, lj4 = (tid & 15) * 4;    // B-loader mapping
    float acc[4][4] = {};
    for (int k0 = 0; k0 < DMODEL; k0 += 16) {
        float4 av = make_float4(0.f, 0.f, 0.f, 0.f);
        int ar = m0 + lrow;
        if (ar < M) {
            int pr = rowidx ? rowidx[ar] : ar;
            av = *(const float4*)(g_X + (size_t)pr * DMODEL + k0 + lk4);
        }
        As[lk4 + 0][lrow] = av.x; As[lk4 + 1][lrow] = av.y;
        As[lk4 + 2][lrow] = av.z; As[lk4 + 3][lrow] = av.w;
        float4 bv = *(const float4*)(W + (size_t)(k0 + lkb) * Nn + n0 + lj4);
        *(float4*)&Bs[lkb][lj4] = bv;
        __syncthreads();
        #pragma unroll
        for (int k = 0; k < 16; k++) {
            float4 a4 = *(const float4*)&As[k][ty * 4];
            float4 b4 = *(const float4*)&Bs[k][tx * 4];
            float a_[4] = {a4.x, a4.y, a4.z, a4.w};
            float b_[4] = {b4.x, b4.y, b4.z, b4.w};
            #pragma unroll
            for (int r = 0; r < 4; r++)
                #pragma unroll
                for (int c = 0; c < 4; c++) acc[r][c] += a_[r] * b_[c];
        }
        __syncthreads();
    }
    #pragma unroll
    for (int r = 0; r < 4; r++) {
        int grow = m0 + ty * 4 + r;
        if (grow >= M) continue;
        #pragma unroll
        for (int c = 0; c < 4; c++) {
            int col = n0 + tx * 4 + c;
            float z = acc[r][c] + bias[col];
            float y = 0.5f * z * (1.0f + erff(z * 0.70710678118654752f));
            g_H[(size_t)grow * Nn + col] = y;
        }
    }
}

// ---------------- LayerNorm in place on g_H, block = Dh threads ----------------
__global__ void ln_inplace_k(const float* __restrict__ g, const float* __restrict__ beta) {
    int row = blockIdx.x;
    int t = threadIdx.x;
    int K = blockDim.x;
    __shared__ float red[256];
    float x = g_H[(size_t)row * K + t];
    red[t] = x; __syncthreads();
    for (int o = K >> 1; o > 0; o >>= 1) { if (t < o) red[t] += red[t + o]; __syncthreads(); }
    float mean = red[0] / (float)K;
    __syncthreads();
    float d = x - mean;
    red[t] = d * d; __syncthreads();
    for (int o = K >> 1; o > 0; o >>= 1) { if (t < o) red[t] += red[t + o]; __syncthreads(); }
    float var = red[0] / (float)K;
    g_H[(size_t)row * K + t] = d * rsqrtf(var + 1e-12f) * g[t] + beta[t];
}

// ---------------- GEMM 2: fused logits + softmax partial stats ----------------
// logits[i,v] = H[i,:] . emb[v,:] + bias[v]; per 64x64 tile emit per-row (max, sumexp, sumlogit)
__global__ void gemm_nt_stats_k(const float* __restrict__ emb, const float* __restrict__ vbias,
                                int M, int V, int K) {
    __shared__ __align__(16) float As[16][68];
    __shared__ __align__(16) float Bs[16][68];
    int m0 = blockIdx.y * 64, n0 = blockIdx.x * 64;
    int tid = threadIdx.x;
    int tx = tid & 15, ty = tid >> 4;
    int lrow = tid >> 2, lk4 = (tid & 3) * 4;
    float acc[4][4] = {};
    for (int k0 = 0; k0 < K; k0 += 16) {
        float4 av = make_float4(0.f, 0.f, 0.f, 0.f);
        int ar = m0 + lrow;
        if (ar < M) av = *(const float4*)(g_H + (size_t)ar * K + k0 + lk4);
        As[lk4 + 0][lrow] = av.x; As[lk4 + 1][lrow] = av.y;
        As[lk4 + 2][lrow] = av.z; As[lk4 + 3][lrow] = av.w;
        float4 bv = make_float4(0.f, 0.f, 0.f, 0.f);
        int br = n0 + lrow;
        if (br < V) bv = *(const float4*)(emb + (size_t)br * K + k0 + lk4);
        Bs[lk4 + 0][lrow] = bv.x; Bs[lk4 + 1][lrow] = bv.y;
        Bs[lk4 + 2][lrow] = bv.z; Bs[lk4 + 3][lrow] = bv.w;
        __syncthreads();
        #pragma unroll
        for (int k = 0; k < 16; k++) {
            float4 a4 = *(const float4*)&As[k][ty * 4];
            float4 b4 = *(const float4*)&Bs[k][tx * 4];
            float a_[4] = {a4.x, a4.y, a4.z, a4.w};
            float b_[4] = {b4.x, b4.y, b4.z, b4.w};
            #pragma unroll
            for (int r = 0; r < 4; r++)
                #pragma unroll
                for (int c = 0; c < 4; c++) acc[r][c] += a_[r] * b_[c];
        }
        __syncthreads();
    }
    // per-row stats across the 64 columns (16 tx lanes x 4 cols)
    #pragma unroll
    for (int r = 0; r < 4; r++) {
        float z[4];
        bool val[4];
        float mloc = -INFINITY;
        #pragma unroll
        for (int c = 0; c < 4; c++) {
            int v = n0 + tx * 4 + c;
            val[c] = (v < V);
            z[c] = val[c] ? (acc[r][c] + vbias[v]) : -INFINITY;
            if (val[c]) mloc = fmaxf(mloc, z[c]);
        }
        #pragma unroll
        for (int o = 8; o > 0; o >>= 1)
            mloc = fmaxf(mloc, __shfl_xor_sync(0xffffffffu, mloc, o));
        float sloc = 0.f, slloc = 0.f;
        #pragma unroll
        for (int c = 0; c < 4; c++) {
            if (val[c]) { sloc += __expf(z[c] - mloc); slloc += z[c]; }
        }
        #pragma unroll
        for (int o = 8; o > 0; o >>= 1) {
            sloc += __shfl_xor_sync(0xffffffffu, sloc, o);
            slloc += __shfl_xor_sync(0xffffffffu, slloc, o);
        }
        if (tx == 0) {
            int grow = m0 + ty * 4 + r;
            if (grow < M) {
                size_t off = (size_t)blockIdx.x * M + grow;
                g_pm[off] = mloc;
                g_ps[off] = sloc;
                g_psl[off] = slloc;
            }
        }
    }
}

// ---------------- per-row merge of partials + target logit + loss accumulation ----------------
__global__ void reduce_softmax_k(const float* __restrict__ emb, const float* __restrict__ vbias,
                                 const int* __restrict__ labels, const int* __restrict__ tsel,
                                 int M, int V, int K, int nVB, int accoff) {
    int row = blockIdx.x;
    int tid = threadIdx.x;   // 128 threads
    float m = -INFINITY, s = 0.f, sl = 0.f;
    for (int vb = tid; vb < nVB; vb += 128) {
        size_t off = (size_t)vb * M + row;
        float mp = g_pm[off];
        if (mp > -INFINITY) {
            float nm = fmaxf(m, mp);
            s = s * __expf(m - nm) + g_ps[off] * __expf(mp - nm);
            m = nm;
        }
        sl += g_psl[off];
    }
    __shared__ float sm[128], ss[128], ssl[128], sd[128];
    sm[tid] = m; ss[tid] = s; ssl[tid] = sl;
    __syncthreads();
    for (int o = 64; o > 0; o >>= 1) {
        if (tid < o) {
            float m1 = sm[tid], s1 = ss[tid];
            float m2 = sm[tid + o], s2 = ss[tid + o];
            float nm = fmaxf(m1, m2);
            float ns = 0.f;
            if (m1 > -INFINITY) ns += s1 * __expf(m1 - nm);
            if (m2 > -INFINITY) ns += s2 * __expf(m2 - nm);
            sm[tid] = nm; ss[tid] = ns; ssl[tid] += ssl[tid + o];
        }
        __syncthreads();
    }
    // target logit: dot(H[row], emb[tgt]) + bias[tgt]
    int tgt = labels[tsel[row]];
    float d = 0.f;
    for (int k = tid; k < K; k += 128)
        d += g_H[(size_t)row * K + k] * emb[(size_t)tgt * K + k];
    sd[tid] = d; __syncthreads();
    for (int o = 64; o > 0; o >>= 1) { if (tid < o) sd[tid] += sd[tid + o]; __syncthreads(); }
    if (tid == 0) {
        float logZ = sm[0] + logf(ss[0]);
        float tlogit = sd[0] + vbias[tgt];
        float nll = logZ - tlogit;
        float smooth = (float)V * logZ - ssl[0];
        atomicAdd(&g_acc[accoff], nll);
        atomicAdd(&g_acc[accoff + 1], smooth);
    }
}

// ---------------- affix head: z = H @ emb^T + bias, fused BCE-with-logits sum ----------------
__global__ void gemm_nt_bce_k(const float* __restrict__ emb, const float* __restrict__ vbias,
                              const float* __restrict__ aprob, const int* __restrict__ tsel,
                              const int* __restrict__ asel, int M, int V, int K) {
    __shared__ __align__(16) float As[16][68];
    __shared__ __align__(16) float Bs[16][68];
    __shared__ float red[256];
    int m0 = blockIdx.y * 64, n0 = blockIdx.x * 64;
    int tid = threadIdx.x;
    int tx = tid & 15, ty = tid >> 4;
    int lrow = tid >> 2, lk4 = (tid & 3) * 4;
    float acc[4][4] = {};
    for (int k0 = 0; k0 < K; k0 += 16) {
        float4 av = make_float4(0.f, 0.f, 0.f, 0.f);
        int ar = m0 + lrow;
        if (ar < M) av = *(const float4*)(g_H + (size_t)ar * K + k0 + lk4);
        As[lk4 + 0][lrow] = av.x; As[lk4 + 1][lrow] = av.y;
        As[lk4 + 2][lrow] = av.z; As[lk4 + 3][lrow] = av.w;
        float4 bv = make_float4(0.f, 0.f, 0.f, 0.f);
        int br = n0 + lrow;
        if (br < V) bv = *(const float4*)(emb + (size_t)br * K + k0 + lk4);
        Bs[lk4 + 0][lrow] = bv.x; Bs[lk4 + 1][lrow] = bv.y;
        Bs[lk4 + 2][lrow] = bv.z; Bs[lk4 + 3][lrow] = bv.w;
        __syncthreads();
        #pragma unroll
        for (int k = 0; k < 16; k++) {
            float4 a4 = *(const float4*)&As[k][ty * 4];
            float4 b4 = *(const float4*)&Bs[k][tx * 4];
            float a_[4] = {a4.x, a4.y, a4.z, a4.w};
            float b_[4] = {b4.x, b4.y, b4.z, b4.w};
            #pragma unroll
            for (int r = 0; r < 4; r++)
                #pragma unroll
                for (int c = 0; c < 4; c++) acc[r][c] += a_[r] * b_[c];
        }
        __syncthreads();
    }
    float lsum = 0.f;
    #pragma unroll
    for (int r = 0; r < 4; r++) {
        int grow = m0 + ty * 4 + r;
        if (grow < M) {
            int trow = tsel[asel[grow]];
            #pragma unroll
            for (int c = 0; c < 4; c++) {
                int v = n0 + tx * 4 + c;
                if (v < V) {
                    float z = acc[r][c] + vbias[v];
                    float t = aprob[(size_t)trow * 360 + v];
                    lsum += fmaxf(z, 0.f) - z * t + log1pf(__expf(-fabsf(z)));
                }
            }
        }
    }
    red[tid] = lsum; __syncthreads();
    for (int o = 128; o > 0; o >>= 1) { if (tid < o) red[tid] += red[tid + o]; __syncthreads(); }
    if (tid == 0) atomicAdd(&g_acc[6], red[0]);
}

// ---------------- finalize: assemble the 7 output scalars ----------------
__global__ void finalize_k(float* __restrict__ out, int T, int Ta) {
    if (threadIdx.x != 0 || blockIdx.x != 0) return;
    const int Vs[3] = {50000, 200, 400};
    for (int h = 0; h < 3; h++) {
        float nll_m = g_acc[2 * h] / (float)T;
        float sm_m  = g_acc[2 * h + 1] / (float)T;
        float eps_i = 0.1f / (float)(Vs[h] - 1);
        out[h] = (1.0f - 0.1f - eps_i) * nll_m + eps_i * sm_m;
        out[4 + h] = nll_m;
    }
    out[3] = g_acc[6] / ((float)Ta * 360.0f);
}

// ---------------- launch ----------------
extern "C" void kernel_launch(void* const* d_in, const int* in_sizes, int n_in,
                              void* d_out, int out_size) {
    const float* hid    = (const float*)d_in[0];
    const float* aprob  = (const float*)d_in[1];
    const int* stems    = (const int*)d_in[2];
    const int* postags  = (const int*)d_in[3];
    const int* morphs   = (const int*)d_in[4];
    const int* hsel     = (const int*)d_in[5];
    const int* tsel     = (const int*)d_in[6];
    const int* asel     = (const int*)d_in[7];
    const float* stem_emb  = (const float*)d_in[8];
    const float* stem_W    = (const float*)d_in[9];
    const float* stem_b    = (const float*)d_in[10];
    const float* stem_g    = (const float*)d_in[11];
    const float* stem_beta = (const float*)d_in[12];
    const float* stem_bias = (const float*)d_in[13];
    const float* pos_emb   = (const float*)d_in[14];
    const float* pos_W     = (const float*)d_in[15];
    const float* pos_b     = (const float*)d_in[16];
    const float* pos_g     = (const float*)d_in[17];
    const float* pos_beta  = (const float*)d_in[18];
    const float* pos_bias  = (const float*)d_in[19];
    const float* morph_emb = (const float*)d_in[20];
    const float* morph_W   = (const float*)d_in[21];
    const float* morph_b   = (const float*)d_in[22];
    const float* morph_g   = (const float*)d_in[23];
    const float* morph_beta= (const float*)d_in[24];
    const float* morph_bias= (const float*)d_in[25];
    const float* aff_emb   = (const float*)d_in[26];
    const float* aff_W     = (const float*)d_in[27];
    const float* aff_b     = (const float*)d_in[28];
    const float* aff_g     = (const float*)d_in[29];
    const float* aff_beta  = (const float*)d_in[30];
    const float* aff_bias  = (const float*)d_in[31];
    float* out = (float*)d_out;

    int T  = in_sizes[5];
    int Ta = in_sizes[7];
    int mT = (T + 63) / 64;
    int mTa = (Ta + 63) / 64;

    zero_acc_k<<<1, 32>>>();
    gather_x_k<<<T, 192>>>(hid, hsel);

    // ---- stem head: Dh=256, V=50000 ----
    {
        const int Dh = 256, V = 50000, nvb = (V + 63) / 64;
        gemm_nn_gelu_k<<<dim3(Dh / 64, mT), 256>>>(stem_W, stem_b, nullptr, T, Dh);
        ln_inplace_k<<<T, Dh>>>(stem_g, stem_beta);
        gemm_nt_stats_k<<<dim3(nvb, mT), 256>>>(stem_emb, stem_bias, T, V, Dh);
        reduce_softmax_k<<<T, 128>>>(stem_emb, stem_bias, stems, tsel, T, V, Dh, nvb, 0);
    }
    // ---- pos head: Dh=128, V=200 ----
    {
        const int Dh = 128, V = 200, nvb = (V + 63) / 64;
        gemm_nn_gelu_k<<<dim3(Dh / 64, mT), 256>>>(pos_W, pos_b, nullptr, T, Dh);
        ln_inplace_k<<<T, Dh>>>(pos_g, pos_beta);
        gemm_nt_stats_k<<<dim3(nvb, mT), 256>>>(pos_emb, pos_bias, T, V, Dh);
        reduce_softmax_k<<<T, 128>>>(pos_emb, pos_bias, postags, tsel, T, V, Dh, nvb, 2);
    }
    // ---- morph head: Dh=128, V=400 ----
    {
        const int Dh = 128, V = 400, nvb = (V + 63) / 64;
        gemm_nn_gelu_k<<<dim3(Dh / 64, mT), 256>>>(morph_W, morph_b, nullptr, T, Dh);
        ln_inplace_k<<<T, Dh>>>(morph_g, morph_beta);
        gemm_nt_stats_k<<<dim3(nvb, mT), 256>>>(morph_emb, morph_bias, T, V, Dh);
        reduce_softmax_k<<<T, 128>>>(morph_emb, morph_bias, morphs, tsel, T, V, Dh, nvb, 4);
    }
    // ---- affix head: Dh=128, V=360, rows = X[asel[i]] ----
    {
        const int Dh = 128, V = 360;
        gemm_nn_gelu_k<<<dim3(Dh / 64, mTa), 256>>>(aff_W, aff_b, asel, Ta, Dh);
        ln_inplace_k<<<Ta, Dh>>>(aff_g, aff_beta);
        gemm_nt_bce_k<<<dim3((V + 63) / 64, mTa), 256>>>(aff_emb, aff_bias, aprob, tsel, asel, Ta, V, Dh);
    }

    finalize_k<<<1, 32>>>(out, T, Ta);
}

// round 2
// speedup vs baseline: 2.1237x; 2.1237x over previous
#include <cuda_runtime.h>
#include <math.h>
#include <stdint.h>
#include <stddef.h>

// ---------------- problem constants ----------------
#define NSEQ 8
#define SSEQ 448
#define DMODEL 768
#define MAXT 3584          // >= N*(S-1) = 3576
#define MAXVB 782          // scratch sized for old 64-wide blocking; 128-wide needs <= 391

// ---------------- device scratch (no allocs allowed) ----------------
__device__ float g_X[MAXT * DMODEL];          // gathered predictor states  [T,768]
__device__ float g_H[MAXT * 256];             // head-transform output (row stride = Dh of current head)
__device__ float g_pm[MAXVB * MAXT];          // partial max     [nVB, T]
__device__ float g_ps[MAXVB * MAXT];          // partial sumexp  [nVB, T]
__device__ float g_psl[MAXVB * MAXT];         // partial sum-logits
__device__ float g_acc[16];                   // loss accumulators

// ---------------- helpers ----------------
__device__ __forceinline__ float f2tf32(float x) {
    uint32_t u;
    asm("cvt.rna.tf32.f32 %0, %1;" : "=r"(u) : "f"(x));
    return __uint_as_float(u);
}

__device__ __forceinline__ void mma_tf32(float* c, const uint32_t* a, const uint32_t* b) {
    asm volatile("mma.sync.aligned.m16n8k8.row.col.f32.tf32.tf32.f32 "
                 "{%0,%1,%2,%3}, {%4,%5,%6,%7}, {%8,%9}, {%0,%1,%2,%3};\n"
                 : "+f"(c[0]), "+f"(c[1]), "+f"(c[2]), "+f"(c[3])
                 : "r"(a[0]), "r"(a[1]), "r"(a[2]), "r"(a[3]), "r"(b[0]), "r"(b[1]));
}

// ---------------- small kernels ----------------
__global__ void zero_acc_k() {
    if (threadIdx.x < 16) g_acc[threadIdx.x] = 0.0f;
}

// x[i,:] = tr_hidden[s, n, :] with hsel[i] = n*S + s  (flat = transpose(S,N,D)->(N*S,D))
__global__ void gather_x_k(const float* __restrict__ hid, const int* __restrict__ hsel) {
    int i = blockIdx.x;
    int idx = hsel[i];
    int s = idx % SSEQ;
    int n = idx / SSEQ;
    const float4* src = (const float4*)(hid + ((size_t)s * NSEQ + n) * DMODEL);
    float4* dst = (float4*)(g_X + (size_t)i * DMODEL);
    dst[threadIdx.x] = src[threadIdx.x];   // 192 threads * float4 = 768 floats
}

// ---------------- GEMM 1: H = gelu(X @ W + b), W is [768, Dh] row-major ----------------
__global__ void gemm_nn_gelu_k(const float* __restrict__ W, const float* __restrict__ bias,
                               const int* __restrict__ rowidx, int M, int Nn) {
    __shared__ __align__(16) float As[16][68];
    __shared__ __align__(16) float Bs[16][68];
    int m0 = blockIdx.y * 64, n0 = blockIdx.x * 64;
    int tid = threadIdx.x;
    int tx = tid & 15, ty = tid >> 4;
    int lrow = tid >> 2, lk4 = (tid & 3) * 4;     // A-loader mapping
    int lkb  = tid >> 4, lj4 = (tid & 15) * 4;    // B-loader mapping
    float acc[4][4] = {};
    for (int k0 = 0; k0 < DMODEL; k0 += 16) {
        float4 av = make_float4(0.f, 0.f, 0.f, 0.f);
        int ar = m0 + lrow;
        if (ar < M) {
            int pr = rowidx ? rowidx[ar] : ar;
            av = *(const float4*)(g_X + (size_t)pr * DMODEL + k0 + lk4);
        }
        As[lk4 + 0][lrow] = av.x; As[lk4 + 1][lrow] = av.y;
        As[lk4 + 2][lrow] = av.z; As[lk4 + 3][lrow] = av.w;
        float4 bv = *(const float4*)(W + (size_t)(k0 + lkb) * Nn + n0 + lj4);
        *(float4*)&Bs[lkb][lj4] = bv;
        __syncthreads();
        #pragma unroll
        for (int k = 0; k < 16; k++) {
            float4 a4 = *(const float4*)&As[k][ty * 4];
            float4 b4 = *(const float4*)&Bs[k][tx * 4];
            float a_[4] = {a4.x, a4.y, a4.z, a4.w};
            float b_[4] = {b4.x, b4.y, b4.z, b4.w};
            #pragma unroll
            for (int r = 0; r < 4; r++)
                #pragma unroll
                for (int c = 0; c < 4; c++) acc[r][c] += a_[r] * b_[c];
        }
        __syncthreads();
    }
    #pragma unroll
    for (int r = 0; r < 4; r++) {
        int grow = m0 + ty * 4 + r;
        if (grow >= M) continue;
        #pragma unroll
        for (int c = 0; c < 4; c++) {
            int col = n0 + tx * 4 + c;
            float z = acc[r][c] + bias[col];
            float y = 0.5f * z * (1.0f + erff(z * 0.70710678118654752f));
            g_H[(size_t)grow * Nn + col] = y;
        }
    }
}

// ---------------- LayerNorm in place on g_H, block = Dh threads ----------------
__global__ void ln_inplace_k(const float* __restrict__ g, const float* __restrict__ beta) {
    int row = blockIdx.x;
    int t = threadIdx.x;
    int K = blockDim.x;
    __shared__ float red[256];
    float x = g_H[(size_t)row * K + t];
    red[t] = x; __syncthreads();
    for (int o = K >> 1; o > 0; o >>= 1) { if (t < o) red[t] += red[t + o]; __syncthreads(); }
    float mean = red[0] / (float)K;
    __syncthreads();
    float d = x - mean;
    red[t] = d * d; __syncthreads();
    for (int o = K >> 1; o > 0; o >>= 1) { if (t < o) red[t] += red[t + o]; __syncthreads(); }
    float var = red[0] / (float)K;
    g_H[(size_t)row * K + t] = d * rsqrtf(var + 1e-12f) * g[t] + beta[t];
}

// ---------------- GEMM 2 (TENSOR CORE): fused logits + softmax partial stats ----------------
// logits[i,v] = H[i,:] . emb[v,:] + bias[v]; per 128x128 tile emit per-row (max, sumexp, sumlogit)
// BM=BN=128, BK=32, 256 threads = 8 warps (2 m-warps x 4 n-warps), warp tile 64x32,
// mma.sync.m16n8k8 tf32 (fragments: 4 m-frags x 4 n-frags per warp).
__global__ void __launch_bounds__(256, 1)
gemm_nt_stats_tc(const float* __restrict__ emb, const float* __restrict__ vbias,
                 int M, int V, int K) {
    __shared__ __align__(16) float As[128][36];
    __shared__ __align__(16) float Bs[128][36];
    __shared__ float s_m[4][128], s_s[4][128], s_l[4][128];
    __shared__ float s_bias[128];

    int m0 = blockIdx.y * 128, n0 = blockIdx.x * 128;
    int tid = threadIdx.x;
    int warp = tid >> 5, lane = tid & 31;
    int wm = warp >> 2;        // 0..1
    int wn = warp & 3;         // 0..3
    int gr = lane >> 2;        // group row 0..7
    int gc = lane & 3;         // thread-in-group 0..3

    if (tid < 128) {
        int v = n0 + tid;
        s_bias[tid] = (v < V) ? vbias[v] : 0.0f;
    }

    float acc[4][4][4];
    #pragma unroll
    for (int mf = 0; mf < 4; mf++)
        #pragma unroll
        for (int nf = 0; nf < 4; nf++)
            #pragma unroll
            for (int q = 0; q < 4; q++) acc[mf][nf][q] = 0.0f;

    for (int k0 = 0; k0 < K; k0 += 32) {
        // load A tile (H rows, clamped)
        #pragma unroll
        for (int i = 0; i < 4; i++) {
            int idx = tid + i * 256;
            int row = idx >> 3, c4 = (idx & 7) * 4;
            int gm = m0 + row; if (gm >= M) gm = M - 1;
            float4 v = *(const float4*)(g_H + (size_t)gm * K + k0 + c4);
            v.x = f2tf32(v.x); v.y = f2tf32(v.y); v.z = f2tf32(v.z); v.w = f2tf32(v.w);
            *(float4*)&As[row][c4] = v;
        }
        // load B tile (emb rows, clamped)
        #pragma unroll
        for (int i = 0; i < 4; i++) {
            int idx = tid + i * 256;
            int row = idx >> 3, c4 = (idx & 7) * 4;
            int gn = n0 + row; if (gn >= V) gn = V - 1;
            float4 v = *(const float4*)(emb + (size_t)gn * K + k0 + c4);
            v.x = f2tf32(v.x); v.y = f2tf32(v.y); v.z = f2tf32(v.z); v.w = f2tf32(v.w);
            *(float4*)&Bs[row][c4] = v;
        }
        __syncthreads();
        #pragma unroll
        for (int ks = 0; ks < 32; ks += 8) {
            uint32_t a[4][4], b[4][2];
            #pragma unroll
            for (int mf = 0; mf < 4; mf++) {
                int r = wm * 64 + mf * 16 + gr;
                a[mf][0] = __float_as_uint(As[r][ks + gc]);
                a[mf][1] = __float_as_uint(As[r + 8][ks + gc]);
                a[mf][2] = __float_as_uint(As[r][ks + gc + 4]);
                a[mf][3] = __float_as_uint(As[r + 8][ks + gc + 4]);
            }
            #pragma unroll
            for (int nf = 0; nf < 4; nf++) {
                int nn = wn * 32 + nf * 8 + gr;
                b[nf][0] = __float_as_uint(Bs[nn][ks + gc]);
                b[nf][1] = __float_as_uint(Bs[nn][ks + gc + 4]);
            }
            #pragma unroll
            for (int mf = 0; mf < 4; mf++)
                #pragma unroll
                for (int nf = 0; nf < 4; nf++)
                    mma_tf32(acc[mf][nf], a[mf], b[nf]);
        }
        __syncthreads();
    }

    // epilogue: per-row partial stats over this block's 128 columns
    #pragma unroll
    for (int mf = 0; mf < 4; mf++) {
        #pragma unroll
        for (int h = 0; h < 2; h++) {
            int rowb = wm * 64 + mf * 16 + h * 8 + gr;
            float z[8];
            bool valid[8];
            float mloc = -INFINITY;
            #pragma unroll
            for (int nf = 0; nf < 4; nf++) {
                #pragma unroll
                for (int q = 0; q < 2; q++) {
                    int colb = wn * 32 + nf * 8 + gc * 2 + q;
                    int cv = n0 + colb;
                    int j = nf * 2 + q;
                    valid[j] = (cv < V);
                    float zz = acc[mf][nf][h * 2 + q] + s_bias[colb];
                    z[j] = valid[j] ? zz : -INFINITY;
                    if (valid[j]) mloc = fmaxf(mloc, z[j]);
                }
            }
            mloc = fmaxf(mloc, __shfl_xor_sync(0xffffffffu, mloc, 1));
            mloc = fmaxf(mloc, __shfl_xor_sync(0xffffffffu, mloc, 2));
            float sloc = 0.f, slloc = 0.f;
            #pragma unroll
            for (int j = 0; j < 8; j++) {
                if (valid[j]) { sloc += __expf(z[j] - mloc); slloc += z[j]; }
            }
            sloc  += __shfl_xor_sync(0xffffffffu, sloc, 1);
            sloc  += __shfl_xor_sync(0xffffffffu, sloc, 2);
            slloc += __shfl_xor_sync(0xffffffffu, slloc, 1);
            slloc += __shfl_xor_sync(0xffffffffu, slloc, 2);
            if (gc == 0) {
                s_m[wn][rowb] = mloc;
                s_s[wn][rowb] = sloc;
                s_l[wn][rowb] = slloc;
            }
        }
    }
    __syncthreads();
    if (tid < 128) {
        int grow = m0 + tid;
        if (grow < M) {
            float m = -INFINITY, s = 0.f, sl = 0.f;
            #pragma unroll
            for (int w = 0; w < 4; w++) {
                float mp = s_m[w][tid];
                if (mp > -INFINITY) {
                    float nm = fmaxf(m, mp);
                    s = s * __expf(m - nm) + s_s[w][tid] * __expf(mp - nm);
                    m = nm;
                }
                sl += s_l[w][tid];
            }
            size_t off = (size_t)blockIdx.x * M + grow;
            g_pm[off] = m;
            g_ps[off] = s;
            g_psl[off] = sl;
        }
    }
}

// ---------------- per-row merge of partials + target logit + loss accumulation ----------------
__global__ void reduce_softmax_k(const float* __restrict__ emb, const float* __restrict__ vbias,
                                 const int* __restrict__ labels, const int* __restrict__ tsel,
                                 int M, int V, int K, int nVB, int accoff) {
    int row = blockIdx.x;
    int tid = threadIdx.x;   // 128 threads
    float m = -INFINITY, s = 0.f, sl = 0.f;
    for (int vb = tid; vb < nVB; vb += 128) {
        size_t off = (size_t)vb * M + row;
        float mp = g_pm[off];
        if (mp > -INFINITY) {
            float nm = fmaxf(m, mp);
            s = s * __expf(m - nm) + g_ps[off] * __expf(mp - nm);
            m = nm;
        }
        sl += g_psl[off];
    }
    __shared__ float sm[128], ss[128], ssl[128], sd[128];
    sm[tid] = m; ss[tid] = s; ssl[tid] = sl;
    __syncthreads();
    for (int o = 64; o > 0; o >>= 1) {
        if (tid < o) {
            float m1 = sm[tid], s1 = ss[tid];
            float m2 = sm[tid + o], s2 = ss[tid + o];
            float nm = fmaxf(m1, m2);
            float ns = 0.f;
            if (m1 > -INFINITY) ns += s1 * __expf(m1 - nm);
            if (m2 > -INFINITY) ns += s2 * __expf(m2 - nm);
            sm[tid] = nm; ss[tid] = ns; ssl[tid] += ssl[tid + o];
        }
        __syncthreads();
    }
    // target logit: dot(H[row], emb[tgt]) + bias[tgt]
    int tgt = labels[tsel[row]];
    float d = 0.f;
    for (int k = tid; k < K; k += 128)
        d += g_H[(size_t)row * K + k] * emb[(size_t)tgt * K + k];
    sd[tid] = d; __syncthreads();
    for (int o = 64; o > 0; o >>= 1) { if (tid < o) sd[tid] += sd[tid + o]; __syncthreads(); }
    if (tid == 0) {
        float logZ = sm[0] + logf(ss[0]);
        float tlogit = sd[0] + vbias[tgt];
        float nll = logZ - tlogit;
        float smooth = (float)V * logZ - ssl[0];
        atomicAdd(&g_acc[accoff], nll);
        atomicAdd(&g_acc[accoff + 1], smooth);
    }
}

// ---------------- affix head: z = H @ emb^T + bias, fused BCE-with-logits sum ----------------
__global__ void gemm_nt_bce_k(const float* __restrict__ emb, const float* __restrict__ vbias,
                              const float* __restrict__ aprob, const int* __restrict__ tsel,
                              const int* __restrict__ asel, int M, int V, int K) {
    __shared__ __align__(16) float As[16][68];
    __shared__ __align__(16) float Bs[16][68];
    __shared__ float red[256];
    int m0 = blockIdx.y * 64, n0 = blockIdx.x * 64;
    int tid = threadIdx.x;
    int tx = tid & 15, ty = tid >> 4;
    int lrow = tid >> 2, lk4 = (tid & 3) * 4;
    float acc[4][4] = {};
    for (int k0 = 0; k0 < K; k0 += 16) {
        float4 av = make_float4(0.f, 0.f, 0.f, 0.f);
        int ar = m0 + lrow;
        if (ar < M) av = *(const float4*)(g_H + (size_t)ar * K + k0 + lk4);
        As[lk4 + 0][lrow] = av.x; As[lk4 + 1][lrow] = av.y;
        As[lk4 + 2][lrow] = av.z; As[lk4 + 3][lrow] = av.w;
        float4 bv = make_float4(0.f, 0.f, 0.f, 0.f);
        int br = n0 + lrow;
        if (br < V) bv = *(const float4*)(emb + (size_t)br * K + k0 + lk4);
        Bs[lk4 + 0][lrow] = bv.x; Bs[lk4 + 1][lrow] = bv.y;
        Bs[lk4 + 2][lrow] = bv.z; Bs[lk4 + 3][lrow] = bv.w;
        __syncthreads();
        #pragma unroll
        for (int k = 0; k < 16; k++) {
            float4 a4 = *(const float4*)&As[k][ty * 4];
            float4 b4 = *(const float4*)&Bs[k][tx * 4];
            float a_[4] = {a4.x, a4.y, a4.z, a4.w};
            float b_[4] = {b4.x, b4.y, b4.z, b4.w};
            #pragma unroll
            for (int r = 0; r < 4; r++)
                #pragma unroll
                for (int c = 0; c < 4; c++) acc[r][c] += a_[r] * b_[c];
        }
        __syncthreads();
    }
    float lsum = 0.f;
    #pragma unroll
    for (int r = 0; r < 4; r++) {
        int grow = m0 + ty * 4 + r;
        if (grow < M) {
            int trow = tsel[asel[grow]];
            #pragma unroll
            for (int c = 0; c < 4; c++) {
                int v = n0 + tx * 4 + c;
                if (v < V) {
                    float z = acc[r][c] + vbias[v];
                    float t = aprob[(size_t)trow * 360 + v];
                    lsum += fmaxf(z, 0.f) - z * t + log1pf(__expf(-fabsf(z)));
                }
            }
        }
    }
    red[tid] = lsum; __syncthreads();
    for (int o = 128; o > 0; o >>= 1) { if (tid < o) red[tid] += red[tid + o]; __syncthreads(); }
    if (tid == 0) atomicAdd(&g_acc[6], red[0]);
}

// ---------------- finalize: assemble the 7 output scalars ----------------
__global__ void finalize_k(float* __restrict__ out, int T, int Ta) {
    if (threadIdx.x != 0 || blockIdx.x != 0) return;
    const int Vs[3] = {50000, 200, 400};
    for (int h = 0; h < 3; h++) {
        float nll_m = g_acc[2 * h] / (float)T;
        float sm_m  = g_acc[2 * h + 1] / (float)T;
        float eps_i = 0.1f / (float)(Vs[h] - 1);
        out[h] = (1.0f - 0.1f - eps_i) * nll_m + eps_i * sm_m;
        out[4 + h] = nll_m;
    }
    out[3] = g_acc[6] / ((float)Ta * 360.0f);
}

// ---------------- launch ----------------
extern "C" void kernel_launch(void* const* d_in, const int* in_sizes, int n_in,
                              void* d_out, int out_size) {
    const float* hid    = (const float*)d_in[0];
    const float* aprob  = (const float*)d_in[1];
    const int* stems    = (const int*)d_in[2];
    const int* postags  = (const int*)d_in[3];
    const int* morphs   = (const int*)d_in[4];
    const int* hsel     = (const int*)d_in[5];
    const int* tsel     = (const int*)d_in[6];
    const int* asel     = (const int*)d_in[7];
    const float* stem_emb  = (const float*)d_in[8];
    const float* stem_W    = (const float*)d_in[9];
    const float* stem_b    = (const float*)d_in[10];
    const float* stem_g    = (const float*)d_in[11];
    const float* stem_beta = (const float*)d_in[12];
    const float* stem_bias = (const float*)d_in[13];
    const float* pos_emb   = (const float*)d_in[14];
    const float* pos_W     = (const float*)d_in[15];
    const float* pos_b     = (const float*)d_in[16];
    const float* pos_g     = (const float*)d_in[17];
    const float* pos_beta  = (const float*)d_in[18];
    const float* pos_bias  = (const float*)d_in[19];
    const float* morph_emb = (const float*)d_in[20];
    const float* morph_W   = (const float*)d_in[21];
    const float* morph_b   = (const float*)d_in[22];
    const float* morph_g   = (const float*)d_in[23];
    const float* morph_beta= (const float*)d_in[24];
    const float* morph_bias= (const float*)d_in[25];
    const float* aff_emb   = (const float*)d_in[26];
    const float* aff_W     = (const float*)d_in[27];
    const float* aff_b     = (const float*)d_in[28];
    const float* aff_g     = (const float*)d_in[29];
    const float* aff_beta  = (const float*)d_in[30];
    const float* aff_bias  = (const float*)d_in[31];
    float* out = (float*)d_out;

    int T  = in_sizes[5];
    int Ta = in_sizes[7];
    int mT = (T + 63) / 64;
    int mT128 = (T + 127) / 128;
    int mTa = (Ta + 63) / 64;

    zero_acc_k<<<1, 32>>>();
    gather_x_k<<<T, 192>>>(hid, hsel);

    // ---- stem head: Dh=256, V=50000 ----
    {
        const int Dh = 256, V = 50000, nvb = (V + 127) / 128;
        gemm_nn_gelu_k<<<dim3(Dh / 64, mT), 256>>>(stem_W, stem_b, nullptr, T, Dh);
        ln_inplace_k<<<T, Dh>>>(stem_g, stem_beta);
        gemm_nt_stats_tc<<<dim3(nvb, mT128), 256>>>(stem_emb, stem_bias, T, V, Dh);
        reduce_softmax_k<<<T, 128>>>(stem_emb, stem_bias, stems, tsel, T, V, Dh, nvb, 0);
    }
    // ---- pos head: Dh=128, V=200 ----
    {
        const int Dh = 128, V = 200, nvb = (V + 127) / 128;
        gemm_nn_gelu_k<<<dim3(Dh / 64, mT), 256>>>(pos_W, pos_b, nullptr, T, Dh);
        ln_inplace_k<<<T, Dh>>>(pos_g, pos_beta);
        gemm_nt_stats_tc<<<dim3(nvb, mT128), 256>>>(pos_emb, pos_bias, T, V, Dh);
        reduce_softmax_k<<<T, 128>>>(pos_emb, pos_bias, postags, tsel, T, V, Dh, nvb, 2);
    }
    // ---- morph head: Dh=128, V=400 ----
    {
        const int Dh = 128, V = 400, nvb = (V + 127) / 128;
        gemm_nn_gelu_k<<<dim3(Dh / 64, mT), 256>>>(morph_W, morph_b, nullptr, T, Dh);
        ln_inplace_k<<<T, Dh>>>(morph_g, morph_beta);
        gemm_nt_stats_tc<<<dim3(nvb, mT128), 256>>>(morph_emb, morph_bias, T, V, Dh);
        reduce_softmax_k<<<T, 128>>>(morph_emb, morph_bias, morphs, tsel, T, V, Dh, nvb, 4);
    }
    // ---- affix head: Dh=128, V=360, rows = X[asel[i]] ----
    {
        const int Dh = 128, V = 360;
        gemm_nn_gelu_k<<<dim3(Dh / 64, mTa), 256>>>(aff_W, aff_b, asel, Ta, Dh);
        ln_inplace_k<<<Ta, Dh>>>(aff_g, aff_beta);
        gemm_nt_bce_k<<<dim3((V + 63) / 64, mTa), 256>>>(aff_emb, aff_bias, aprob, tsel, asel, Ta, V, Dh);
    }

    finalize_k<<<1, 32>>>(out, T, Ta);
}

// round 3
// speedup vs baseline: 3.7312x; 1.7569x over previous
#include <cuda_runtime.h>
#include <cuda_bf16.h>
#include <math.h>
#include <stdint.h>
#include <stddef.h>

// ---------------- problem constants ----------------
#define NSEQ 8
#define SSEQ 448
#define DMODEL 768
#define MAXT 3584          // >= N*(S-1) = 3576
#define MAXVB 782
#define MAXV 50000
#define MAXDH 256

// ---------------- device scratch (no allocs allowed) ----------------
__device__ float g_X[MAXT * DMODEL];                 // gathered predictor states  [T,768]
__device__ float g_H[MAXT * MAXDH];                  // head-transform output fp32
__device__ __nv_bfloat16 g_Hb[MAXT * MAXDH];         // bf16 copy of H (post-LN)
__device__ __nv_bfloat16 g_Eb[MAXV * MAXDH];         // bf16 copy of current head's emb
__device__ float g_pm[MAXVB * MAXT];                 // partial max     [nVB, T]
__device__ float g_ps[MAXVB * MAXT];                 // partial sumexp  [nVB, T]
__device__ float g_psl[MAXVB * MAXT];                // partial sum-logits
__device__ float g_acc[16];                          // loss accumulators

// ---------------- asm helpers ----------------
#define CP_ASYNC16(dst, src) \
    asm volatile("cp.async.ca.shared.global [%0], [%1], 16;\n" :: "r"(dst), "l"(src))
#define CP_COMMIT() asm volatile("cp.async.commit_group;\n" ::)
#define CP_WAIT1()  asm volatile("cp.async.wait_group 1;\n" ::)

__device__ __forceinline__ void ldsm_x4(uint32_t* r, uint32_t addr) {
    asm volatile("ldmatrix.sync.aligned.m8n8.x4.shared.b16 {%0,%1,%2,%3}, [%4];"
                 : "=r"(r[0]), "=r"(r[1]), "=r"(r[2]), "=r"(r[3]) : "r"(addr));
}

__device__ __forceinline__ void mma_bf16(float* c, const uint32_t* a, const uint32_t* b) {
    asm volatile("mma.sync.aligned.m16n8k16.row.col.f32.bf16.bf16.f32 "
                 "{%0,%1,%2,%3}, {%4,%5,%6,%7}, {%8,%9}, {%0,%1,%2,%3};\n"
                 : "+f"(c[0]), "+f"(c[1]), "+f"(c[2]), "+f"(c[3])
                 : "r"(a[0]), "r"(a[1]), "r"(a[2]), "r"(a[3]), "r"(b[0]), "r"(b[1]));
}

// ---------------- small kernels ----------------
__global__ void zero_acc_k() {
    if (threadIdx.x < 16) g_acc[threadIdx.x] = 0.0f;
}

__global__ void cvt_bf16_k(const float* __restrict__ src, __nv_bfloat16* __restrict__ dst, int n) {
    int i = blockIdx.x * blockDim.x + threadIdx.x;
    if (i * 4 < n) {
        float4 v = *(const float4*)(src + i * 4);
        __nv_bfloat16 o[4] = {__float2bfloat16_rn(v.x), __float2bfloat16_rn(v.y),
                              __float2bfloat16_rn(v.z), __float2bfloat16_rn(v.w)};
        *(uint64_t*)(dst + i * 4) = *(uint64_t*)o;
    }
}

// x[i,:] = tr_hidden[s, n, :] with hsel[i] = n*S + s
__global__ void gather_x_k(const float* __restrict__ hid, const int* __restrict__ hsel) {
    int i = blockIdx.x;
    int idx = hsel[i];
    int s = idx % SSEQ;
    int n = idx / SSEQ;
    const float4* src = (const float4*)(hid + ((size_t)s * NSEQ + n) * DMODEL);
    float4* dst = (float4*)(g_X + (size_t)i * DMODEL);
    dst[threadIdx.x] = src[threadIdx.x];
}

// ---------------- GEMM 1: H = gelu(X @ W + b), W is [768, Dh] row-major ----------------
__global__ void gemm_nn_gelu_k(const float* __restrict__ W, const float* __restrict__ bias,
                               const int* __restrict__ rowidx, int M, int Nn) {
    __shared__ __align__(16) float As[16][68];
    __shared__ __align__(16) float Bs[16][68];
    int m0 = blockIdx.y * 64, n0 = blockIdx.x * 64;
    int tid = threadIdx.x;
    int tx = tid & 15, ty = tid >> 4;
    int lrow = tid >> 2, lk4 = (tid & 3) * 4;
    int lkb  = tid >> 4, lj4 = (tid & 15) * 4;
    float acc[4][4] = {};
    for (int k0 = 0; k0 < DMODEL; k0 += 16) {
        float4 av = make_float4(0.f, 0.f, 0.f, 0.f);
        int ar = m0 + lrow;
        if (ar < M) {
            int pr = rowidx ? rowidx[ar] : ar;
            av = *(const float4*)(g_X + (size_t)pr * DMODEL + k0 + lk4);
        }
        As[lk4 + 0][lrow] = av.x; As[lk4 + 1][lrow] = av.y;
        As[lk4 + 2][lrow] = av.z; As[lk4 + 3][lrow] = av.w;
        float4 bv = *(const float4*)(W + (size_t)(k0 + lkb) * Nn + n0 + lj4);
        *(float4*)&Bs[lkb][lj4] = bv;
        __syncthreads();
        #pragma unroll
        for (int k = 0; k < 16; k++) {
            float4 a4 = *(const float4*)&As[k][ty * 4];
            float4 b4 = *(const float4*)&Bs[k][tx * 4];
            float a_[4] = {a4.x, a4.y, a4.z, a4.w};
            float b_[4] = {b4.x, b4.y, b4.z, b4.w};
            #pragma unroll
            for (int r = 0; r < 4; r++)
                #pragma unroll
                for (int c = 0; c < 4; c++) acc[r][c] += a_[r] * b_[c];
        }
        __syncthreads();
    }
    #pragma unroll
    for (int r = 0; r < 4; r++) {
        int grow = m0 + ty * 4 + r;
        if (grow >= M) continue;
        #pragma unroll
        for (int c = 0; c < 4; c++) {
            int col = n0 + tx * 4 + c;
            float z = acc[r][c] + bias[col];
            float y = 0.5f * z * (1.0f + erff(z * 0.70710678118654752f));
            g_H[(size_t)grow * Nn + col] = y;
        }
    }
}

// ---------------- LayerNorm in place on g_H + bf16 copy ----------------
__global__ void ln_inplace_k(const float* __restrict__ g, const float* __restrict__ beta) {
    int row = blockIdx.x;
    int t = threadIdx.x;
    int K = blockDim.x;
    __shared__ float red[256];
    float x = g_H[(size_t)row * K + t];
    red[t] = x; __syncthreads();
    for (int o = K >> 1; o > 0; o >>= 1) { if (t < o) red[t] += red[t + o]; __syncthreads(); }
    float mean = red[0] / (float)K;
    __syncthreads();
    float d = x - mean;
    red[t] = d * d; __syncthreads();
    for (int o = K >> 1; o > 0; o >>= 1) { if (t < o) red[t] += red[t + o]; __syncthreads(); }
    float var = red[0] / (float)K;
    float y = d * rsqrtf(var + 1e-12f) * g[t] + beta[t];
    g_H[(size_t)row * K + t] = y;
    g_Hb[(size_t)row * K + t] = __float2bfloat16_rn(y);
}

// ---------------- GEMM 2 (bf16 tensor core, pipelined): fused logits + softmax stats --------
// BM=BN=128, BK=32, 256 threads = 8 warps (2 m x 4 n), warp tile 64x32.
// cp.async double buffer; ldmatrix.x4 fragment loads; mma m16n8k16 bf16.
#define BKP 40   // padded row stride in bf16 elements (80 bytes)
__global__ void __launch_bounds__(256)
gemm_nt_stats_bf16(const float* __restrict__ vbias, int M, int V, int K) {
    __shared__ __align__(16) __nv_bfloat16 As[2][128 * BKP];
    __shared__ __align__(16) __nv_bfloat16 Bs[2][128 * BKP];
    __shared__ float s_m[4][128], s_s[4][128], s_l[4][128];
    __shared__ float s_bias[128];

    int m0 = blockIdx.y * 128, n0 = blockIdx.x * 128;
    int tid = threadIdx.x;
    int warp = tid >> 5, lane = tid & 31;
    int wm = warp >> 2, wn = warp & 3;
    int gr = lane >> 2, gc = lane & 3;

    if (tid < 128) {
        int v = n0 + tid;
        s_bias[tid] = (v < V) ? vbias[v] : 0.0f;
    }

    uint32_t a_base = (uint32_t)__cvta_generic_to_shared(&As[0][0]);
    uint32_t b_base = (uint32_t)__cvta_generic_to_shared(&Bs[0][0]);
    const uint32_t STAGE = 128 * BKP * 2;   // bytes per stage

    int lrow = tid >> 2;          // 0..63? no: tid>>2 -> 0..63 for 256 threads... need 0..127
    // loader: 512 16B-chunks per operand per stage; 256 threads x 2 iters
    // idx = tid + i*256; row = idx>>2 (0..127); c16 = idx&3

    float acc[4][4][4];
    #pragma unroll
    for (int mf = 0; mf < 4; mf++)
        #pragma unroll
        for (int nf = 0; nf < 4; nf++)
            #pragma unroll
            for (int q = 0; q < 4; q++) acc[mf][nf][q] = 0.0f;

    int nc = K >> 5;   // chunks of 32

    // ---- stage loader (lambda-free) ----
    // issues 4 cp.async per thread for stage s, chunk c
    #define LOAD_STAGE(c, s) do {                                              \
        int k0 = (c) << 5;                                                     \
        _Pragma("unroll")                                                      \
        for (int i = 0; i < 2; i++) {                                          \
            int idx = tid + i * 256;                                           \
            int row = idx >> 2, c16 = idx & 3;                                 \
            int gm = m0 + row; if (gm >= M) gm = M - 1;                        \
            const __nv_bfloat16* sa = g_Hb + (size_t)gm * K + k0 + c16 * 8;    \
            uint32_t da = a_base + (s) * STAGE + (row * BKP + c16 * 8) * 2;    \
            CP_ASYNC16(da, sa);                                                \
            int gn = n0 + row; if (gn >= V) gn = V - 1;                        \
            const __nv_bfloat16* sb = g_Eb + (size_t)gn * K + k0 + c16 * 8;    \
            uint32_t db = b_base + (s) * STAGE + (row * BKP + c16 * 8) * 2;    \
            CP_ASYNC16(db, sb);                                                \
        }                                                                      \
    } while (0)

    LOAD_STAGE(0, 0);
    CP_COMMIT();

    // precomputed ldmatrix lane addressing
    int a_row_off = wm * 64 + ((lane >> 3) & 1) * 8 + (lane & 7);   // + mf*16
    int a_col     = (lane >> 4) * 8;                                 // element col, + ks*16
    int b_row_off = wn * 32 + ((lane >> 4) & 1) * 8 + (lane & 7);   // + p*16
    int b_col     = ((lane >> 3) & 1) * 8;                           // + ks*16

    for (int c = 0; c < nc; c++) {
        int cur = c & 1;
        if (c + 1 < nc) LOAD_STAGE(c + 1, cur ^ 1);
        CP_COMMIT();
        CP_WAIT1();
        __syncthreads();

        uint32_t abase_s = a_base + cur * STAGE;
        uint32_t bbase_s = b_base + cur * STAGE;
        #pragma unroll
        for (int ks = 0; ks < 2; ks++) {
            uint32_t af[4][4], bf[2][4];
            #pragma unroll
            for (int mf = 0; mf < 4; mf++) {
                uint32_t addr = abase_s + ((a_row_off + mf * 16) * BKP + a_col + ks * 16) * 2;
                ldsm_x4(af[mf], addr);
            }
            #pragma unroll
            for (int p = 0; p < 2; p++) {
                uint32_t addr = bbase_s + ((b_row_off + p * 16) * BKP + b_col + ks * 16) * 2;
                ldsm_x4(bf[p], addr);
            }
            #pragma unroll
            for (int mf = 0; mf < 4; mf++)
                #pragma unroll
                for (int nf = 0; nf < 4; nf++)
                    mma_bf16(acc[mf][nf], af[mf], &bf[nf >> 1][(nf & 1) * 2]);
        }
        __syncthreads();
    }

    // epilogue: per-row partial stats over this block's 128 columns
    #pragma unroll
    for (int mf = 0; mf < 4; mf++) {
        #pragma unroll
        for (int h = 0; h < 2; h++) {
            int rowb = wm * 64 + mf * 16 + h * 8 + gr;
            float z[8];
            bool valid[8];
            float mloc = -INFINITY;
            #pragma unroll
            for (int nf = 0; nf < 4; nf++) {
                #pragma unroll
                for (int q = 0; q < 2; q++) {
                    int colb = wn * 32 + nf * 8 + gc * 2 + q;
                    int cv = n0 + colb;
                    int j = nf * 2 + q;
                    valid[j] = (cv < V);
                    float zz = acc[mf][nf][h * 2 + q] + s_bias[colb];
                    z[j] = valid[j] ? zz : -INFINITY;
                    if (valid[j]) mloc = fmaxf(mloc, z[j]);
                }
            }
            mloc = fmaxf(mloc, __shfl_xor_sync(0xffffffffu, mloc, 1));
            mloc = fmaxf(mloc, __shfl_xor_sync(0xffffffffu, mloc, 2));
            float sloc = 0.f, slloc = 0.f;
            #pragma unroll
            for (int j = 0; j < 8; j++) {
                if (valid[j]) { sloc += __expf(z[j] - mloc); slloc += z[j]; }
            }
            sloc  += __shfl_xor_sync(0xffffffffu, sloc, 1);
            sloc  += __shfl_xor_sync(0xffffffffu, sloc, 2);
            slloc += __shfl_xor_sync(0xffffffffu, slloc, 1);
            slloc += __shfl_xor_sync(0xffffffffu, slloc, 2);
            if (gc == 0) {
                s_m[wn][rowb] = mloc;
                s_s[wn][rowb] = sloc;
                s_l[wn][rowb] = slloc;
            }
        }
    }
    __syncthreads();
    if (tid < 128) {
        int grow = m0 + tid;
        if (grow < M) {
            float m = -INFINITY, s = 0.f, sl = 0.f;
            #pragma unroll
            for (int w = 0; w < 4; w++) {
                float mp = s_m[w][tid];
                if (mp > -INFINITY) {
                    float nm = fmaxf(m, mp);
                    s = s * __expf(m - nm) + s_s[w][tid] * __expf(mp - nm);
                    m = nm;
                }
                sl += s_l[w][tid];
            }
            size_t off = (size_t)blockIdx.x * M + grow;
            g_pm[off] = m;
            g_ps[off] = s;
            g_psl[off] = sl;
        }
    }
}

// ---------------- per-row merge of partials + target logit + loss accumulation ----------------
__global__ void reduce_softmax_k(const float* __restrict__ emb, const float* __restrict__ vbias,
                                 const int* __restrict__ labels, const int* __restrict__ tsel,
                                 int M, int V, int K, int nVB, int accoff) {
    int row = blockIdx.x;
    int tid = threadIdx.x;   // 128 threads
    float m = -INFINITY, s = 0.f, sl = 0.f;
    for (int vb = tid; vb < nVB; vb += 128) {
        size_t off = (size_t)vb * M + row;
        float mp = g_pm[off];
        if (mp > -INFINITY) {
            float nm = fmaxf(m, mp);
            s = s * __expf(m - nm) + g_ps[off] * __expf(mp - nm);
            m = nm;
        }
        sl += g_psl[off];
    }
    __shared__ float sm[128], ss[128], ssl[128], sd[128];
    sm[tid] = m; ss[tid] = s; ssl[tid] = sl;
    __syncthreads();
    for (int o = 64; o > 0; o >>= 1) {
        if (tid < o) {
            float m1 = sm[tid], s1 = ss[tid];
            float m2 = sm[tid + o], s2 = ss[tid + o];
            float nm = fmaxf(m1, m2);
            float ns = 0.f;
            if (m1 > -INFINITY) ns += s1 * __expf(m1 - nm);
            if (m2 > -INFINITY) ns += s2 * __expf(m2 - nm);
            sm[tid] = nm; ss[tid] = ns; ssl[tid] += ssl[tid + o];
        }
        __syncthreads();
    }
    // target logit in bf16 (consistent with logits used for logZ)
    int tgt = labels[tsel[row]];
    float d = 0.f;
    for (int k = tid; k < K; k += 128)
        d += __bfloat162float(g_Hb[(size_t)row * K + k]) *
             __bfloat162float(g_Eb[(size_t)tgt * K + k]);
    sd[tid] = d; __syncthreads();
    for (int o = 64; o > 0; o >>= 1) { if (tid < o) sd[tid] += sd[tid + o]; __syncthreads(); }
    if (tid == 0) {
        float logZ = sm[0] + logf(ss[0]);
        float tlogit = sd[0] + vbias[tgt];
        float nll = logZ - tlogit;
        float smooth = (float)V * logZ - ssl[0];
        atomicAdd(&g_acc[accoff], nll);
        atomicAdd(&g_acc[accoff + 1], smooth);
    }
}

// ---------------- affix head: z = H @ emb^T + bias, fused BCE-with-logits sum ----------------
__global__ void gemm_nt_bce_k(const float* __restrict__ emb, const float* __restrict__ vbias,
                              const float* __restrict__ aprob, const int* __restrict__ tsel,
                              const int* __restrict__ asel, int M, int V, int K) {
    __shared__ __align__(16) float As[16][68];
    __shared__ __align__(16) float Bs[16][68];
    __shared__ float red[256];
    int m0 = blockIdx.y * 64, n0 = blockIdx.x * 64;
    int tid = threadIdx.x;
    int tx = tid & 15, ty = tid >> 4;
    int lrow = tid >> 2, lk4 = (tid & 3) * 4;
    float acc[4][4] = {};
    for (int k0 = 0; k0 < K; k0 += 16) {
        float4 av = make_float4(0.f, 0.f, 0.f, 0.f);
        int ar = m0 + lrow;
        if (ar < M) av = *(const float4*)(g_H + (size_t)ar * K + k0 + lk4);
        As[lk4 + 0][lrow] = av.x; As[lk4 + 1][lrow] = av.y;
        As[lk4 + 2][lrow] = av.z; As[lk4 + 3][lrow] = av.w;
        float4 bv = make_float4(0.f, 0.f, 0.f, 0.f);
        int br = n0 + lrow;
        if (br < V) bv = *(const float4*)(emb + (size_t)br * K + k0 + lk4);
        Bs[lk4 + 0][lrow] = bv.x; Bs[lk4 + 1][lrow] = bv.y;
        Bs[lk4 + 2][lrow] = bv.z; Bs[lk4 + 3][lrow] = bv.w;
        __syncthreads();
        #pragma unroll
        for (int k = 0; k < 16; k++) {
            float4 a4 = *(const float4*)&As[k][ty * 4];
            float4 b4 = *(const float4*)&Bs[k][tx * 4];
            float a_[4] = {a4.x, a4.y, a4.z, a4.w};
            float b_[4] = {b4.x, b4.y, b4.z, b4.w};
            #pragma unroll
            for (int r = 0; r < 4; r++)
                #pragma unroll
                for (int c = 0; c < 4; c++) acc[r][c] += a_[r] * b_[c];
        }
        __syncthreads();
    }
    float lsum = 0.f;
    #pragma unroll
    for (int r = 0; r < 4; r++) {
        int grow = m0 + ty * 4 + r;
        if (grow < M) {
            int trow = tsel[asel[grow]];
            #pragma unroll
            for (int c = 0; c < 4; c++) {
                int v = n0 + tx * 4 + c;
                if (v < V) {
                    float z = acc[r][c] + vbias[v];
                    float t = aprob[(size_t)trow * 360 + v];
                    lsum += fmaxf(z, 0.f) - z * t + log1pf(__expf(-fabsf(z)));
                }
            }
        }
    }
    red[tid] = lsum; __syncthreads();
    for (int o = 128; o > 0; o >>= 1) { if (tid < o) red[tid] += red[tid + o]; __syncthreads(); }
    if (tid == 0) atomicAdd(&g_acc[6], red[0]);
}

// ---------------- finalize: assemble the 7 output scalars ----------------
__global__ void finalize_k(float* __restrict__ out, int T, int Ta) {
    if (threadIdx.x != 0 || blockIdx.x != 0) return;
    const int Vs[3] = {50000, 200, 400};
    for (int h = 0; h < 3; h++) {
        float nll_m = g_acc[2 * h] / (float)T;
        float sm_m  = g_acc[2 * h + 1] / (float)T;
        float eps_i = 0.1f / (float)(Vs[h] - 1);
        out[h] = (1.0f - 0.1f - eps_i) * nll_m + eps_i * sm_m;
        out[4 + h] = nll_m;
    }
    out[3] = g_acc[6] / ((float)Ta * 360.0f);
}

// ---------------- launch ----------------
extern "C" void kernel_launch(void* const* d_in, const int* in_sizes, int n_in,
                              void* d_out, int out_size) {
    const float* hid    = (const float*)d_in[0];
    const float* aprob  = (const float*)d_in[1];
    const int* stems    = (const int*)d_in[2];
    const int* postags  = (const int*)d_in[3];
    const int* morphs   = (const int*)d_in[4];
    const int* hsel     = (const int*)d_in[5];
    const int* tsel     = (const int*)d_in[6];
    const int* asel     = (const int*)d_in[7];
    const float* stem_emb  = (const float*)d_in[8];
    const float* stem_W    = (const float*)d_in[9];
    const float* stem_b    = (const float*)d_in[10];
    const float* stem_g    = (const float*)d_in[11];
    const float* stem_beta = (const float*)d_in[12];
    const float* stem_bias = (const float*)d_in[13];
    const float* pos_emb   = (const float*)d_in[14];
    const float* pos_W     = (const float*)d_in[15];
    const float* pos_b     = (const float*)d_in[16];
    const float* pos_g     = (const float*)d_in[17];
    const float* pos_beta  = (const float*)d_in[18];
    const float* pos_bias  = (const float*)d_in[19];
    const float* morph_emb = (const float*)d_in[20];
    const float* morph_W   = (const float*)d_in[21];
    const float* morph_b   = (const float*)d_in[22];
    const float* morph_g   = (const float*)d_in[23];
    const float* morph_beta= (const float*)d_in[24];
    const float* morph_bias= (const float*)d_in[25];
    const float* aff_emb   = (const float*)d_in[26];
    const float* aff_W     = (const float*)d_in[27];
    const float* aff_b     = (const float*)d_in[28];
    const float* aff_g     = (const float*)d_in[29];
    const float* aff_beta  = (const float*)d_in[30];
    const float* aff_bias  = (const float*)d_in[31];
    float* out = (float*)d_out;

    int T  = in_sizes[5];
    int Ta = in_sizes[7];
    int mT = (T + 63) / 64;
    int mT128 = (T + 127) / 128;
    int mTa = (Ta + 63) / 64;

    __nv_bfloat16* dEb;
    cudaGetSymbolAddress((void**)&dEb, g_Eb);

    zero_acc_k<<<1, 32>>>();
    gather_x_k<<<T, 192>>>(hid, hsel);

    // ---- stem head: Dh=256, V=50000 ----
    {
        const int Dh = 256, V = 50000, nvb = (V + 127) / 128;
        gemm_nn_gelu_k<<<dim3(Dh / 64, mT), 256>>>(stem_W, stem_b, nullptr, T, Dh);
        ln_inplace_k<<<T, Dh>>>(stem_g, stem_beta);
        cvt_bf16_k<<<(V * Dh / 4 + 255) / 256, 256>>>(stem_emb, dEb, V * Dh);
        gemm_nt_stats_bf16<<<dim3(nvb, mT128), 256>>>(stem_bias, T, V, Dh);
        reduce_softmax_k<<<T, 128>>>(stem_emb, stem_bias, stems, tsel, T, V, Dh, nvb, 0);
    }
    // ---- pos head: Dh=128, V=200 ----
    {
        const int Dh = 128, V = 200, nvb = (V + 127) / 128;
        gemm_nn_gelu_k<<<dim3(Dh / 64, mT), 256>>>(pos_W, pos_b, nullptr, T, Dh);
        ln_inplace_k<<<T, Dh>>>(pos_g, pos_beta);
        cvt_bf16_k<<<(V * Dh / 4 + 255) / 256, 256>>>(pos_emb, dEb, V * Dh);
        gemm_nt_stats_bf16<<<dim3(nvb, mT128), 256>>>(pos_bias, T, V, Dh);
        reduce_softmax_k<<<T, 128>>>(pos_emb, pos_bias, postags, tsel, T, V, Dh, nvb, 2);
    }
    // ---- morph head: Dh=128, V=400 ----
    {
        const int Dh = 128, V = 400, nvb = (V + 127) / 128;
        gemm_nn_gelu_k<<<dim3(Dh / 64, mT), 256>>>(morph_W, morph_b, nullptr, T, Dh);
        ln_inplace_k<<<T, Dh>>>(morph_g, morph_beta);
        cvt_bf16_k<<<(V * Dh / 4 + 255) / 256, 256>>>(morph_emb, dEb, V * Dh);
        gemm_nt_stats_bf16<<<dim3(nvb, mT128), 256>>>(morph_bias, T, V, Dh);
        reduce_softmax_k<<<T, 128>>>(morph_emb, morph_bias, morphs, tsel, T, V, Dh, nvb, 4);
    }
    // ---- affix head: Dh=128, V=360, rows = X[asel[i]] ----
    {
        const int Dh = 128, V = 360;
        gemm_nn_gelu_k<<<dim3(Dh / 64, mTa), 256>>>(aff_W, aff_b, asel, Ta, Dh);
        ln_inplace_k<<<Ta, Dh>>>(aff_g, aff_beta);
        gemm_nt_bce_k<<<dim3((V + 63) / 64, mTa), 256>>>(aff_emb, aff_bias, aprob, tsel, asel, Ta, V, Dh);
    }

    finalize_k<<<1, 32>>>(out, T, Ta);
}

// round 5
// speedup vs baseline: 4.8780x; 1.3074x over previous
#include <cuda_runtime.h>
#include <cuda_bf16.h>
#include <math.h>
#include <stdint.h>
#include <stddef.h>

// ---------------- problem constants ----------------
#define NSEQ 8
#define SSEQ 448
#define DMODEL 768
#define MAXT 3584          // >= N*(S-1) = 3576
#define MAXVB 782
#define MAXV 50000
#define HTOT 640           // 256 + 128 + 128 + 128 concatenated head dims

// ---------------- device scratch (no allocs allowed) ----------------
__device__ __nv_bfloat16 g_Xb[MAXT * DMODEL];        // gathered predictor states bf16
__device__ __nv_bfloat16 g_Wb[HTOT * DMODEL];        // W^T concat bf16: [n=640][k=768]
__device__ float g_bc[HTOT];                         // concatenated transform biases
__device__ float g_H[MAXT * HTOT];                   // transform output fp32 (post-gelu, post-LN)
__device__ __nv_bfloat16 g_Hb[MAXT * HTOT];          // bf16 copy of H (post-LN)
__device__ __nv_bfloat16 g_Eb[MAXV * 256];           // bf16 copy of current head's emb
__device__ float g_pm[MAXVB * MAXT];                 // partial max     [nVB, T]
__device__ float g_ps[MAXVB * MAXT];                 // partial sumexp  [nVB, T]
__device__ float g_psl[MAXVB * MAXT];                // partial sum-logits
__device__ float g_acc[16];                          // loss accumulators

// ---------------- asm helpers ----------------
#define CP_ASYNC16(dst, src) \
    asm volatile("cp.async.cg.shared.global [%0], [%1], 16;\n" :: "r"(dst), "l"(src))
#define CP_COMMIT() asm volatile("cp.async.commit_group;\n" ::)
#define CP_WAIT1()  asm volatile("cp.async.wait_group 1;\n" ::)

__device__ __forceinline__ void ldsm_x4(uint32_t* r, uint32_t addr) {
    asm volatile("ldmatrix.sync.aligned.m8n8.x4.shared.b16 {%0,%1,%2,%3}, [%4];"
                 : "=r"(r[0]), "=r"(r[1]), "=r"(r[2]), "=r"(r[3]) : "r"(addr));
}

__device__ __forceinline__ void mma_bf16(float* c, const uint32_t* a, const uint32_t* b) {
    asm volatile("mma.sync.aligned.m16n8k16.row.col.f32.bf16.bf16.f32 "
                 "{%0,%1,%2,%3}, {%4,%5,%6,%7}, {%8,%9}, {%0,%1,%2,%3};\n"
                 : "+f"(c[0]), "+f"(c[1]), "+f"(c[2]), "+f"(c[3])
                 : "r"(a[0]), "r"(a[1]), "r"(a[2]), "r"(a[3]), "r"(b[0]), "r"(b[1]));
}

#define BKP 40   // padded smem row stride in bf16 elements (80 bytes)

// stage loader: 128 rows x 32 cols of A and B (bf16), 4 cp.async/thread
__device__ __forceinline__ void load_tile_pair(
    const __nv_bfloat16* __restrict__ A, int lda, int Arows, int m0,
    const __nv_bfloat16* __restrict__ B, int ldb, int Brows, int n0,
    int k0, uint32_t a_st, uint32_t b_st, int tid)
{
    #pragma unroll
    for (int i = 0; i < 2; i++) {
        int idx = tid + i * 256;
        int row = idx >> 2, c16 = idx & 3;
        int gm = m0 + row; if (gm >= Arows) gm = Arows - 1;
        CP_ASYNC16(a_st + (row * BKP + c16 * 8) * 2, A + (size_t)gm * lda + k0 + c16 * 8);
        int gn = n0 + row; if (gn >= Brows) gn = Brows - 1;
        CP_ASYNC16(b_st + (row * BKP + c16 * 8) * 2, B + (size_t)gn * ldb + k0 + c16 * 8);
    }
}

// ---------------- small kernels ----------------
__global__ void zero_acc_k() {
    if (threadIdx.x < 16) g_acc[threadIdx.x] = 0.0f;
}

__global__ void cvt_bf16_k(const float* __restrict__ src, __nv_bfloat16* __restrict__ dst, int n) {
    int i = blockIdx.x * blockDim.x + threadIdx.x;
    if (i * 4 < n) {
        float4 v = *(const float4*)(src + i * 4);
        __nv_bfloat16 o[4] = {__float2bfloat16_rn(v.x), __float2bfloat16_rn(v.y),
                              __float2bfloat16_rn(v.z), __float2bfloat16_rn(v.w)};
        *(uint64_t*)(dst + i * 4) = *(uint64_t*)o;
    }
}

// pack one head's W [768, Dh] transposed into g_Wb[(noff+n)*768+k], bias into g_bc
__global__ void cvt_w_k(const float* __restrict__ W, const float* __restrict__ b,
                        int Dh, int noff) {
    int t = blockIdx.x * blockDim.x + threadIdx.x;
    int total = Dh * DMODEL;
    if (t < total) {
        int n = t / DMODEL, k = t % DMODEL;
        g_Wb[(size_t)(noff + n) * DMODEL + k] = __float2bfloat16_rn(W[(size_t)k * Dh + n]);
    }
    if (t < Dh) g_bc[noff + t] = b[t];
}

// x[i,:] = tr_hidden[s, n, :] with hsel[i] = n*S + s ; write bf16
__global__ void gather_x_k(const float* __restrict__ hid, const int* __restrict__ hsel) {
    int i = blockIdx.x;
    int idx = hsel[i];
    int s = idx % SSEQ;
    int n = idx / SSEQ;
    float4 v = ((const float4*)(hid + ((size_t)s * NSEQ + n) * DMODEL))[threadIdx.x];
    __nv_bfloat16 o[4] = {__float2bfloat16_rn(v.x), __float2bfloat16_rn(v.y),
                          __float2bfloat16_rn(v.z), __float2bfloat16_rn(v.w)};
    *(uint64_t*)(g_Xb + (size_t)i * DMODEL + threadIdx.x * 4) = *(uint64_t*)o;
}

// ---------------- transform GEMM (bf16 TC): g_H = gelu(Xb @ Wb^T + bc), out stride 640 ----
__global__ void __launch_bounds__(256)
gemm_tc_gelu(int M) {
    __shared__ __align__(16) __nv_bfloat16 As[2][128 * BKP];
    __shared__ __align__(16) __nv_bfloat16 Bs[2][128 * BKP];
    int m0 = blockIdx.y * 128, n0 = blockIdx.x * 128;
    int tid = threadIdx.x;
    int warp = tid >> 5, lane = tid & 31;
    int wm = warp >> 2, wn = warp & 3;
    int gr = lane >> 2, gc = lane & 3;

    uint32_t a_base = (uint32_t)__cvta_generic_to_shared(&As[0][0]);
    uint32_t b_base = (uint32_t)__cvta_generic_to_shared(&Bs[0][0]);
    const uint32_t STAGE = 128 * BKP * 2;

    float acc[4][4][4];
    #pragma unroll
    for (int mf = 0; mf < 4; mf++)
        #pragma unroll
        for (int nf = 0; nf < 4; nf++)
            #pragma unroll
            for (int q = 0; q < 4; q++) acc[mf][nf][q] = 0.0f;

    const int nc = DMODEL / 32;   // 24
    load_tile_pair(g_Xb, DMODEL, M, m0, g_Wb, DMODEL, HTOT, n0, 0, a_base, b_base, tid);
    CP_COMMIT();

    int a_row_off = wm * 64 + ((lane >> 3) & 1) * 8 + (lane & 7);
    int a_col     = (lane >> 4) * 8;
    int b_row_off = wn * 32 + ((lane >> 4) & 1) * 8 + (lane & 7);
    int b_col     = ((lane >> 3) & 1) * 8;

    for (int c = 0; c < nc; c++) {
        int cur = c & 1;
        if (c + 1 < nc)
            load_tile_pair(g_Xb, DMODEL, M, m0, g_Wb, DMODEL, HTOT, n0,
                           (c + 1) << 5, a_base + (cur ^ 1) * STAGE, b_base + (cur ^ 1) * STAGE, tid);
        CP_COMMIT();
        CP_WAIT1();
        __syncthreads();
        uint32_t abase_s = a_base + cur * STAGE;
        uint32_t bbase_s = b_base + cur * STAGE;
        #pragma unroll
        for (int ks = 0; ks < 2; ks++) {
            uint32_t af[4][4], bf[2][4];
            #pragma unroll
            for (int mf = 0; mf < 4; mf++)
                ldsm_x4(af[mf], abase_s + ((a_row_off + mf * 16) * BKP + a_col + ks * 16) * 2);
            #pragma unroll
            for (int p = 0; p < 2; p++)
                ldsm_x4(bf[p], bbase_s + ((b_row_off + p * 16) * BKP + b_col + ks * 16) * 2);
            #pragma unroll
            for (int mf = 0; mf < 4; mf++)
                #pragma unroll
                for (int nf = 0; nf < 4; nf++)
                    mma_bf16(acc[mf][nf], af[mf], &bf[nf >> 1][(nf & 1) * 2]);
        }
        __syncthreads();
    }

    // epilogue: z = acc + bc[col]; gelu; store fp32 to g_H (stride 640)
    #pragma unroll
    for (int mf = 0; mf < 4; mf++) {
        #pragma unroll
        for (int h = 0; h < 2; h++) {
            int grow = m0 + wm * 64 + mf * 16 + h * 8 + gr;
            if (grow < M) {
                #pragma unroll
                for (int nf = 0; nf < 4; nf++) {
                    int col = n0 + wn * 32 + nf * 8 + gc * 2;
                    float z0 = acc[mf][nf][h * 2 + 0] + g_bc[col];
                    float z1 = acc[mf][nf][h * 2 + 1] + g_bc[col + 1];
                    float y0 = 0.5f * z0 * (1.0f + erff(z0 * 0.70710678118654752f));
                    float y1 = 0.5f * z1 * (1.0f + erff(z1 * 0.70710678118654752f));
                    *(float2*)(g_H + (size_t)grow * HTOT + col) = make_float2(y0, y1);
                }
            }
        }
    }
}

// ---------------- warp-per-row LayerNorm on g_H segment [hoff, hoff+DH), writes fp32+bf16 ---
template <int DH>
__global__ void ln_warp_k(const float* __restrict__ g, const float* __restrict__ beta,
                          int hoff, int T) {
    int w = threadIdx.x >> 5, lane = threadIdx.x & 31;
    int row = blockIdx.x * 8 + w;
    if (row >= T) return;
    const int E = DH / 32;
    float* base = g_H + (size_t)row * HTOT + hoff;
    float v[E];
    float s = 0.f;
    #pragma unroll
    for (int i = 0; i < E; i++) { v[i] = base[lane + i * 32]; s += v[i]; }
    #pragma unroll
    for (int o = 16; o > 0; o >>= 1) s += __shfl_xor_sync(0xffffffffu, s, o);
    float mean = s / (float)DH;
    float q = 0.f;
    #pragma unroll
    for (int i = 0; i < E; i++) { float d = v[i] - mean; q += d * d; }
    #pragma unroll
    for (int o = 16; o > 0; o >>= 1) q += __shfl_xor_sync(0xffffffffu, q, o);
    float r = rsqrtf(q / (float)DH + 1e-12f);
    #pragma unroll
    for (int i = 0; i < E; i++) {
        float y = (v[i] - mean) * r * g[lane + i * 32] + beta[lane + i * 32];
        base[lane + i * 32] = y;
        g_Hb[(size_t)row * HTOT + hoff + lane + i * 32] = __float2bfloat16_rn(y);
    }
}

// ---------------- stats GEMM (bf16 TC, 2 CTA/SM): fused logits + softmax partials ----------
__global__ void __launch_bounds__(256, 2)
gemm_nt_stats_bf16(const __nv_bfloat16* __restrict__ A, int lda,
                   const float* __restrict__ vbias, int M, int V, int K) {
    __shared__ __align__(16) __nv_bfloat16 As[2][128 * BKP];
    __shared__ __align__(16) __nv_bfloat16 Bs[2][128 * BKP];
    __shared__ float s_m[4][128], s_s[4][128], s_l[4][128];
    __shared__ float s_bias[128];

    int m0 = blockIdx.y * 128, n0 = blockIdx.x * 128;
    int tid = threadIdx.x;
    int warp = tid >> 5, lane = tid & 31;
    int wm = warp >> 2, wn = warp & 3;
    int gr = lane >> 2, gc = lane & 3;

    if (tid < 128) {
        int v = n0 + tid;
        s_bias[tid] = (v < V) ? vbias[v] : 0.0f;
    }

    uint32_t a_base = (uint32_t)__cvta_generic_to_shared(&As[0][0]);
    uint32_t b_base = (uint32_t)__cvta_generic_to_shared(&Bs[0][0]);
    const uint32_t STAGE = 128 * BKP * 2;

    float acc[4][4][4];
    #pragma unroll
    for (int mf = 0; mf < 4; mf++)
        #pragma unroll
        for (int nf = 0; nf < 4; nf++)
            #pragma unroll
            for (int q = 0; q < 4; q++) acc[mf][nf][q] = 0.0f;

    int nc = K >> 5;
    load_tile_pair(A, lda, M, m0, g_Eb, K, V, n0, 0, a_base, b_base, tid);
    CP_COMMIT();

    int a_row_off = wm * 64 + ((lane >> 3) & 1) * 8 + (lane & 7);
    int a_col     = (lane >> 4) * 8;
    int b_row_off = wn * 32 + ((lane >> 4) & 1) * 8 + (lane & 7);
    int b_col     = ((lane >> 3) & 1) * 8;

    for (int c = 0; c < nc; c++) {
        int cur = c & 1;
        if (c + 1 < nc)
            load_tile_pair(A, lda, M, m0, g_Eb, K, V, n0, (c + 1) << 5,
                           a_base + (cur ^ 1) * STAGE, b_base + (cur ^ 1) * STAGE, tid);
        CP_COMMIT();
        CP_WAIT1();
        __syncthreads();
        uint32_t abase_s = a_base + cur * STAGE;
        uint32_t bbase_s = b_base + cur * STAGE;
        #pragma unroll
        for (int ks = 0; ks < 2; ks++) {
            uint32_t af[4][4], bf[2][4];
            #pragma unroll
            for (int mf = 0; mf < 4; mf++)
                ldsm_x4(af[mf], abase_s + ((a_row_off + mf * 16) * BKP + a_col + ks * 16) * 2);
            #pragma unroll
            for (int p = 0; p < 2; p++)
                ldsm_x4(bf[p], bbase_s + ((b_row_off + p * 16) * BKP + b_col + ks * 16) * 2);
            #pragma unroll
            for (int mf = 0; mf < 4; mf++)
                #pragma unroll
                for (int nf = 0; nf < 4; nf++)
                    mma_bf16(acc[mf][nf], af[mf], &bf[nf >> 1][(nf & 1) * 2]);
        }
        __syncthreads();
    }

    // epilogue: per-row partial stats over this block's 128 columns
    #pragma unroll
    for (int mf = 0; mf < 4; mf++) {
        #pragma unroll
        for (int h = 0; h < 2; h++) {
            int rowb = wm * 64 + mf * 16 + h * 8 + gr;
            float z[8];
            bool valid[8];
            float mloc = -INFINITY;
            #pragma unroll
            for (int nf = 0; nf < 4; nf++) {
                #pragma unroll
                for (int q = 0; q < 2; q++) {
                    int colb = wn * 32 + nf * 8 + gc * 2 + q;
                    int cv = n0 + colb;
                    int j = nf * 2 + q;
                    valid[j] = (cv < V);
                    float zz = acc[mf][nf][h * 2 + q] + s_bias[colb];
                    z[j] = valid[j] ? zz : -INFINITY;
                    if (valid[j]) mloc = fmaxf(mloc, z[j]);
                }
            }
            mloc = fmaxf(mloc, __shfl_xor_sync(0xffffffffu, mloc, 1));
            mloc = fmaxf(mloc, __shfl_xor_sync(0xffffffffu, mloc, 2));
            float sloc = 0.f, slloc = 0.f;
            #pragma unroll
            for (int j = 0; j < 8; j++) {
                if (valid[j]) { sloc += __expf(z[j] - mloc); slloc += z[j]; }
            }
            sloc  += __shfl_xor_sync(0xffffffffu, sloc, 1);
            sloc  += __shfl_xor_sync(0xffffffffu, sloc, 2);
            slloc += __shfl_xor_sync(0xffffffffu, slloc, 1);
            slloc += __shfl_xor_sync(0xffffffffu, slloc, 2);
            if (gc == 0) {
                s_m[wn][rowb] = mloc;
                s_s[wn][rowb] = sloc;
                s_l[wn][rowb] = slloc;
            }
        }
    }
    __syncthreads();
    if (tid < 128) {
        int grow = m0 + tid;
        if (grow < M) {
            float m = -INFINITY, s = 0.f, sl = 0.f;
            #pragma unroll
            for (int w = 0; w < 4; w++) {
                float mp = s_m[w][tid];
                if (mp > -INFINITY) {
                    float nm = fmaxf(m, mp);
                    s = s * __expf(m - nm) + s_s[w][tid] * __expf(mp - nm);
                    m = nm;
                }
                sl += s_l[w][tid];
            }
            size_t off = (size_t)blockIdx.x * M + grow;
            g_pm[off] = m;
            g_ps[off] = s;
            g_psl[off] = sl;
        }
    }
}

// ---------------- per-row merge of partials + target logit + loss accumulation ----------------
__global__ void reduce_softmax_k(const float* __restrict__ vbias,
                                 const int* __restrict__ labels, const int* __restrict__ tsel,
                                 int M, int V, int K, int nVB, int hoff, int accoff) {
    int row = blockIdx.x;
    int tid = threadIdx.x;   // 128 threads
    float m = -INFINITY, s = 0.f, sl = 0.f;
    for (int vb = tid; vb < nVB; vb += 128) {
        size_t off = (size_t)vb * M + row;
        float mp = g_pm[off];
        if (mp > -INFINITY) {
            float nm = fmaxf(m, mp);
            s = s * __expf(m - nm) + g_ps[off] * __expf(mp - nm);
            m = nm;
        }
        sl += g_psl[off];
    }
    __shared__ float sm[128], ss[128], ssl[128], sd[128];
    sm[tid] = m; ss[tid] = s; ssl[tid] = sl;
    __syncthreads();
    for (int o = 64; o > 0; o >>= 1) {
        if (tid < o) {
            float m1 = sm[tid], s1 = ss[tid];
            float m2 = sm[tid + o], s2 = ss[tid + o];
            float nm = fmaxf(m1, m2);
            float ns = 0.f;
            if (m1 > -INFINITY) ns += s1 * __expf(m1 - nm);
            if (m2 > -INFINITY) ns += s2 * __expf(m2 - nm);
            sm[tid] = nm; ss[tid] = ns; ssl[tid] += ssl[tid + o];
        }
        __syncthreads();
    }
    // target logit in bf16 (consistent with logits used for logZ)
    int tgt = labels[tsel[row]];
    float d = 0.f;
    for (int k = tid; k < K; k += 128)
        d += __bfloat162float(g_Hb[(size_t)row * HTOT + hoff + k]) *
             __bfloat162float(g_Eb[(size_t)tgt * K + k]);
    sd[tid] = d; __syncthreads();
    for (int o = 64; o > 0; o >>= 1) { if (tid < o) sd[tid] += sd[tid + o]; __syncthreads(); }
    if (tid == 0) {
        float logZ = sm[0] + logf(ss[0]);
        float tlogit = sd[0] + vbias[tgt];
        float nll = logZ - tlogit;
        float smooth = (float)V * logZ - ssl[0];
        atomicAdd(&g_acc[accoff], nll);
        atomicAdd(&g_acc[accoff + 1], smooth);
    }
}

// ---------------- affix head: z = H[asel]@emb^T + bias, fused BCE-with-logits sum ----------
__global__ void gemm_nt_bce_k(const float* __restrict__ emb, const float* __restrict__ vbias,
                              const float* __restrict__ aprob, const int* __restrict__ tsel,
                              const int* __restrict__ asel, int M, int V, int K, int hoff) {
    __shared__ __align__(16) float As[16][68];
    __shared__ __align__(16) float Bs[16][68];
    __shared__ float red[256];
    int m0 = blockIdx.y * 64, n0 = blockIdx.x * 64;
    int tid = threadIdx.x;
    int tx = tid & 15, ty = tid >> 4;
    int lrow = tid >> 2, lk4 = (tid & 3) * 4;
    float acc[4][4] = {};
    for (int k0 = 0; k0 < K; k0 += 16) {
        float4 av = make_float4(0.f, 0.f, 0.f, 0.f);
        int ar = m0 + lrow;
        if (ar < M) {
            int pr = asel[ar];
            av = *(const float4*)(g_H + (size_t)pr * HTOT + hoff + k0 + lk4);
        }
        As[lk4 + 0][lrow] = av.x; As[lk4 + 1][lrow] = av.y;
        As[lk4 + 2][lrow] = av.z; As[lk4 + 3][lrow] = av.w;
        float4 bv = make_float4(0.f, 0.f, 0.f, 0.f);
        int br = n0 + lrow;
        if (br < V) bv = *(const float4*)(emb + (size_t)br * K + k0 + lk4);
        Bs[lk4 + 0][lrow] = bv.x; Bs[lk4 + 1][lrow] = bv.y;
        Bs[lk4 + 2][lrow] = bv.z; Bs[lk4 + 3][lrow] = bv.w;
        __syncthreads();
        #pragma unroll
        for (int k = 0; k < 16; k++) {
            float4 a4 = *(const float4*)&As[k][ty * 4];
            float4 b4 = *(const float4*)&Bs[k][tx * 4];
            float a_[4] = {a4.x, a4.y, a4.z, a4.w};
            float b_[4] = {b4.x, b4.y, b4.z, b4.w};
            #pragma unroll
            for (int r = 0; r < 4; r++)
                #pragma unroll
                for (int c = 0; c < 4; c++) acc[r][c] += a_[r] * b_[c];
        }
        __syncthreads();
    }
    float lsum = 0.f;
    #pragma unroll
    for (int r = 0; r < 4; r++) {
        int grow = m0 + ty * 4 + r;
        if (grow < M) {
            int trow = tsel[asel[grow]];
            #pragma unroll
            for (int c = 0; c < 4; c++) {
                int v = n0 + tx * 4 + c;
                if (v < V) {
                    float z = acc[r][c] + vbias[v];
                    float t = aprob[(size_t)trow * 360 + v];
                    lsum += fmaxf(z, 0.f) - z * t + log1pf(__expf(-fabsf(z)));
                }
            }
        }
    }
    red[tid] = lsum; __syncthreads();
    for (int o = 128; o > 0; o >>= 1) { if (tid < o) red[tid] += red[tid + o]; __syncthreads(); }
    if (tid == 0) atomicAdd(&g_acc[6], red[0]);
}

// ---------------- finalize: assemble the 7 output scalars ----------------
__global__ void finalize_k(float* __restrict__ out, int T, int Ta) {
    if (threadIdx.x != 0 || blockIdx.x != 0) return;
    const int Vs[3] = {50000, 200, 400};
    for (int h = 0; h < 3; h++) {
        float nll_m = g_acc[2 * h] / (float)T;
        float sm_m  = g_acc[2 * h + 1] / (float)T;
        float eps_i = 0.1f / (float)(Vs[h] - 1);
        out[h] = (1.0f - 0.1f - eps_i) * nll_m + eps_i * sm_m;
        out[4 + h] = nll_m;
    }
    out[3] = g_acc[6] / ((float)Ta * 360.0f);
}

// ---------------- launch ----------------
extern "C" void kernel_launch(void* const* d_in, const int* in_sizes, int n_in,
                              void* d_out, int out_size) {
    const float* hid    = (const float*)d_in[0];
    const float* aprob  = (const float*)d_in[1];
    const int* stems    = (const int*)d_in[2];
    const int* postags  = (const int*)d_in[3];
    const int* morphs   = (const int*)d_in[4];
    const int* hsel     = (const int*)d_in[5];
    const int* tsel     = (const int*)d_in[6];
    const int* asel     = (const int*)d_in[7];
    const float* stem_emb  = (const float*)d_in[8];
    const float* stem_W    = (const float*)d_in[9];
    const float* stem_b    = (const float*)d_in[10];
    const float* stem_g    = (const float*)d_in[11];
    const float* stem_beta = (const float*)d_in[12];
    const float* stem_bias = (const float*)d_in[13];
    const float* pos_emb   = (const float*)d_in[14];
    const float* pos_W     = (const float*)d_in[15];
    const float* pos_b     = (const float*)d_in[16];
    const float* pos_g     = (const float*)d_in[17];
    const float* pos_beta  = (const float*)d_in[18];
    const float* pos_bias  = (const float*)d_in[19];
    const float* morph_emb = (const float*)d_in[20];
    const float* morph_W   = (const float*)d_in[21];
    const float* morph_b   = (const float*)d_in[22];
    const float* morph_g   = (const float*)d_in[23];
    const float* morph_beta= (const float*)d_in[24];
    const float* morph_bias= (const float*)d_in[25];
    const float* aff_emb   = (const float*)d_in[26];
    const float* aff_W     = (const float*)d_in[27];
    const float* aff_b     = (const float*)d_in[28];
    const float* aff_g     = (const float*)d_in[29];
    const float* aff_beta  = (const float*)d_in[30];
    const float* aff_bias  = (const float*)d_in[31];
    float* out = (float*)d_out;

    int T  = in_sizes[5];
    int Ta = in_sizes[7];
    int mT128 = (T + 127) / 128;
    int mTa = (Ta + 63) / 64;
    int lnb = (T + 7) / 8;

    __nv_bfloat16* dEb;
    __nv_bfloat16* dHb;
    cudaGetSymbolAddress((void**)&dEb, g_Eb);
    cudaGetSymbolAddress((void**)&dHb, g_Hb);

    zero_acc_k<<<1, 32>>>();
    gather_x_k<<<T, 192>>>(hid, hsel);

    // pack transform weights (transposed bf16) + biases
    cvt_w_k<<<(256 * DMODEL + 255) / 256, 256>>>(stem_W,  stem_b,  256, 0);
    cvt_w_k<<<(128 * DMODEL + 255) / 256, 256>>>(pos_W,   pos_b,   128, 256);
    cvt_w_k<<<(128 * DMODEL + 255) / 256, 256>>>(morph_W, morph_b, 128, 384);
    cvt_w_k<<<(128 * DMODEL + 255) / 256, 256>>>(aff_W,   aff_b,   128, 512);

    // batched transform for all 4 heads
    gemm_tc_gelu<<<dim3(HTOT / 128, mT128), 256>>>(T);

    // per-head LN (warp-per-row)
    ln_warp_k<256><<<lnb, 256>>>(stem_g,  stem_beta,  0,   T);
    ln_warp_k<128><<<lnb, 256>>>(pos_g,   pos_beta,   256, T);
    ln_warp_k<128><<<lnb, 256>>>(morph_g, morph_beta, 384, T);
    ln_warp_k<128><<<lnb, 256>>>(aff_g,   aff_beta,   512, T);

    // ---- stem head: Dh=256, V=50000 ----
    {
        const int Dh = 256, V = 50000, nvb = (V + 127) / 128;
        cvt_bf16_k<<<(V * Dh / 4 + 255) / 256, 256>>>(stem_emb, dEb, V * Dh);
        gemm_nt_stats_bf16<<<dim3(nvb, mT128), 256>>>(dHb + 0, HTOT, stem_bias, T, V, Dh);
        reduce_softmax_k<<<T, 128>>>(stem_bias, stems, tsel, T, V, Dh, nvb, 0, 0);
    }
    // ---- pos head: Dh=128, V=200 ----
    {
        const int Dh = 128, V = 200, nvb = (V + 127) / 128;
        cvt_bf16_k<<<(V * Dh / 4 + 255) / 256, 256>>>(pos_emb, dEb, V * Dh);
        gemm_nt_stats_bf16<<<dim3(nvb, mT128), 256>>>(dHb + 256, HTOT, pos_bias, T, V, Dh);
        reduce_softmax_k<<<T, 128>>>(pos_bias, postags, tsel, T, V, Dh, nvb, 256, 2);
    }
    // ---- morph head: Dh=128, V=400 ----
    {
        const int Dh = 128, V = 400, nvb = (V + 127) / 128;
        cvt_bf16_k<<<(V * Dh / 4 + 255) / 256, 256>>>(morph_emb, dEb, V * Dh);
        gemm_nt_stats_bf16<<<dim3(nvb, mT128), 256>>>(dHb + 384, HTOT, morph_bias, T, V, Dh);
        reduce_softmax_k<<<T, 128>>>(morph_bias, morphs, tsel, T, V, Dh, nvb, 384, 4);
    }
    // ---- affix head: Dh=128, V=360, rows = H[asel[i]], BCE ----
    {
        const int Dh = 128, V = 360;
        gemm_nt_bce_k<<<dim3((V + 63) / 64, mTa), 256>>>(aff_emb, aff_bias, aprob, tsel, asel,
                                                         Ta, V, Dh, 512);
    }

    finalize_k<<<1, 32>>>(out, T, Ta);
}

// round 7
// speedup vs baseline: 5.3229x; 1.0912x over previous
#include <cuda_runtime.h>
#include <cuda_bf16.h>
#include <math.h>
#include <stdint.h>
#include <stddef.h>

// ---------------- problem constants ----------------
#define NSEQ 8
#define SSEQ 448
#define DMODEL 768
#define MAXT 3584          // >= N*(S-1) = 3576
#define MAXVB 782
#define MAXV 50000
#define HTOT 640           // 256 + 128 + 128 + 128 concatenated head dims

// ---------------- device scratch (no allocs allowed) ----------------
__device__ __nv_bfloat16 g_Xb[MAXT * DMODEL];        // gathered predictor states bf16
__device__ __nv_bfloat16 g_Wb[HTOT * DMODEL];        // W^T concat bf16: [n=640][k=768]
__device__ float g_bc[HTOT];                         // concatenated transform biases
__device__ float g_H[MAXT * HTOT];                   // transform output fp32 (post-gelu, post-LN)
__device__ __nv_bfloat16 g_Hb[MAXT * HTOT];          // bf16 copy of H (post-LN)
__device__ __nv_bfloat16 g_Eb[MAXV * 256];           // bf16 copy of current head's emb
__device__ float g_pm[MAXVB * MAXT];                 // partial max     [nVB, T]
__device__ float g_ps[MAXVB * MAXT];                 // partial sumexp  [nVB, T]
__device__ float g_psl[MAXVB * MAXT];                // partial sum-logits
__device__ float g_acc[16];                          // loss accumulators

// ---------------- asm helpers ----------------
#define CP_ASYNC16(dst, src) \
    asm volatile("cp.async.cg.shared.global [%0], [%1], 16;\n" :: "r"(dst), "l"(src))
#define CP_COMMIT() asm volatile("cp.async.commit_group;\n" ::)
#define CP_WAIT1()  asm volatile("cp.async.wait_group 1;\n" ::)
#define CP_WAIT2()  asm volatile("cp.async.wait_group 2;\n" ::)

__device__ __forceinline__ void ldsm_x4(uint32_t* r, uint32_t addr) {
    asm volatile("ldmatrix.sync.aligned.m8n8.x4.shared.b16 {%0,%1,%2,%3}, [%4];"
                 : "=r"(r[0]), "=r"(r[1]), "=r"(r[2]), "=r"(r[3]) : "r"(addr));
}

__device__ __forceinline__ void mma_bf16(float* c, const uint32_t* a, const uint32_t* b) {
    asm volatile("mma.sync.aligned.m16n8k16.row.col.f32.bf16.bf16.f32 "
                 "{%0,%1,%2,%3}, {%4,%5,%6,%7}, {%8,%9}, {%0,%1,%2,%3};\n"
                 : "+f"(c[0]), "+f"(c[1]), "+f"(c[2]), "+f"(c[3])
                 : "r"(a[0]), "r"(a[1]), "r"(a[2]), "r"(a[3]), "r"(b[0]), "r"(b[1]));
}

#define BKP 40           // padded smem row stride in bf16 elements (80 bytes)
#define STAGE_B (128 * BKP * 2)   // 10240 bytes per operand per stage
#define NSTAGE 4
#define SMEM_STATS (NSTAGE * STAGE_B * 2 + 3 * 4 * 128 * 4 + 128 * 4)  // 88576 B

// stage loader: 128 rows x 32 cols of A and B (bf16), 4 cp.async/thread
__device__ __forceinline__ void load_tile_pair(
    const __nv_bfloat16* __restrict__ A, int lda, int Arows, int m0,
    const __nv_bfloat16* __restrict__ B, int ldb, int Brows, int n0,
    int k0, uint32_t a_st, uint32_t b_st, int tid)
{
    #pragma unroll
    for (int i = 0; i < 2; i++) {
        int idx = tid + i * 256;
        int row = idx >> 2, c16 = idx & 3;
        int gm = m0 + row; if (gm >= Arows) gm = Arows - 1;
        CP_ASYNC16(a_st + (row * BKP + c16 * 8) * 2, A + (size_t)gm * lda + k0 + c16 * 8);
        int gn = n0 + row; if (gn >= Brows) gn = Brows - 1;
        CP_ASYNC16(b_st + (row * BKP + c16 * 8) * 2, B + (size_t)gn * ldb + k0 + c16 * 8);
    }
}

// ---------------- small kernels ----------------
__global__ void zero_acc_k() {
    if (threadIdx.x < 16) g_acc[threadIdx.x] = 0.0f;
}

__global__ void cvt_bf16_k(const float* __restrict__ src, __nv_bfloat16* __restrict__ dst, int n) {
    int i = blockIdx.x * blockDim.x + threadIdx.x;
    if (i * 4 < n) {
        float4 v = *(const float4*)(src + i * 4);
        __nv_bfloat16 o[4] = {__float2bfloat16_rn(v.x), __float2bfloat16_rn(v.y),
                              __float2bfloat16_rn(v.z), __float2bfloat16_rn(v.w)};
        *(uint64_t*)(dst + i * 4) = *(uint64_t*)o;
    }
}

// pack one head's W [768, Dh] transposed into g_Wb[(noff+n)*768+k], bias into g_bc
__global__ void cvt_w_k(const float* __restrict__ W, const float* __restrict__ b,
                        int Dh, int noff) {
    int t = blockIdx.x * blockDim.x + threadIdx.x;
    int total = Dh * DMODEL;
    if (t < total) {
        int n = t / DMODEL, k = t % DMODEL;
        g_Wb[(size_t)(noff + n) * DMODEL + k] = __float2bfloat16_rn(W[(size_t)k * Dh + n]);
    }
    if (t < Dh) g_bc[noff + t] = b[t];
}

// x[i,:] = tr_hidden[s, n, :] with hsel[i] = n*S + s ; write bf16
__global__ void gather_x_k(const float* __restrict__ hid, const int* __restrict__ hsel) {
    int i = blockIdx.x;
    int idx = hsel[i];
    int s = idx % SSEQ;
    int n = idx / SSEQ;
    float4 v = ((const float4*)(hid + ((size_t)s * NSEQ + n) * DMODEL))[threadIdx.x];
    __nv_bfloat16 o[4] = {__float2bfloat16_rn(v.x), __float2bfloat16_rn(v.y),
                          __float2bfloat16_rn(v.z), __float2bfloat16_rn(v.w)};
    *(uint64_t*)(g_Xb + (size_t)i * DMODEL + threadIdx.x * 4) = *(uint64_t*)o;
}

// ---------------- transform GEMM (bf16 TC): g_H = gelu(Xb @ Wb^T + bc), out stride 640 ----
__global__ void __launch_bounds__(256)
gemm_tc_gelu(int M) {
    __shared__ __align__(16) __nv_bfloat16 As[2][128 * BKP];
    __shared__ __align__(16) __nv_bfloat16 Bs[2][128 * BKP];
    int m0 = blockIdx.y * 128, n0 = blockIdx.x * 128;
    int tid = threadIdx.x;
    int warp = tid >> 5, lane = tid & 31;
    int wm = warp >> 2, wn = warp & 3;
    int gr = lane >> 2, gc = lane & 3;

    uint32_t a_base = (uint32_t)__cvta_generic_to_shared(&As[0][0]);
    uint32_t b_base = (uint32_t)__cvta_generic_to_shared(&Bs[0][0]);
    const uint32_t STAGE = 128 * BKP * 2;

    float acc[4][4][4];
    #pragma unroll
    for (int mf = 0; mf < 4; mf++)
        #pragma unroll
        for (int nf = 0; nf < 4; nf++)
            #pragma unroll
            for (int q = 0; q < 4; q++) acc[mf][nf][q] = 0.0f;

    const int nc = DMODEL / 32;   // 24
    load_tile_pair(g_Xb, DMODEL, M, m0, g_Wb, DMODEL, HTOT, n0, 0, a_base, b_base, tid);
    CP_COMMIT();

    int a_row_off = wm * 64 + ((lane >> 3) & 1) * 8 + (lane & 7);
    int a_col     = (lane >> 4) * 8;
    int b_row_off = wn * 32 + ((lane >> 4) & 1) * 8 + (lane & 7);
    int b_col     = ((lane >> 3) & 1) * 8;

    for (int c = 0; c < nc; c++) {
        int cur = c & 1;
        if (c + 1 < nc)
            load_tile_pair(g_Xb, DMODEL, M, m0, g_Wb, DMODEL, HTOT, n0,
                           (c + 1) << 5, a_base + (cur ^ 1) * STAGE, b_base + (cur ^ 1) * STAGE, tid);
        CP_COMMIT();
        CP_WAIT1();
        __syncthreads();
        uint32_t abase_s = a_base + cur * STAGE;
        uint32_t bbase_s = b_base + cur * STAGE;
        #pragma unroll
        for (int ks = 0; ks < 2; ks++) {
            uint32_t af[4][4], bf[2][4];
            #pragma unroll
            for (int mf = 0; mf < 4; mf++)
                ldsm_x4(af[mf], abase_s + ((a_row_off + mf * 16) * BKP + a_col + ks * 16) * 2);
            #pragma unroll
            for (int p = 0; p < 2; p++)
                ldsm_x4(bf[p], bbase_s + ((b_row_off + p * 16) * BKP + b_col + ks * 16) * 2);
            #pragma unroll
            for (int mf = 0; mf < 4; mf++)
                #pragma unroll
                for (int nf = 0; nf < 4; nf++)
                    mma_bf16(acc[mf][nf], af[mf], &bf[nf >> 1][(nf & 1) * 2]);
        }
        __syncthreads();
    }

    // epilogue: z = acc + bc[col]; gelu; store fp32 to g_H (stride 640)
    #pragma unroll
    for (int mf = 0; mf < 4; mf++) {
        #pragma unroll
        for (int h = 0; h < 2; h++) {
            int grow = m0 + wm * 64 + mf * 16 + h * 8 + gr;
            if (grow < M) {
                #pragma unroll
                for (int nf = 0; nf < 4; nf++) {
                    int col = n0 + wn * 32 + nf * 8 + gc * 2;
                    float z0 = acc[mf][nf][h * 2 + 0] + g_bc[col];
                    float z1 = acc[mf][nf][h * 2 + 1] + g_bc[col + 1];
                    float y0 = 0.5f * z0 * (1.0f + erff(z0 * 0.70710678118654752f));
                    float y1 = 0.5f * z1 * (1.0f + erff(z1 * 0.70710678118654752f));
                    *(float2*)(g_H + (size_t)grow * HTOT + col) = make_float2(y0, y1);
                }
            }
        }
    }
}

// ---------------- warp-per-row LayerNorm on g_H segment [hoff, hoff+DH), writes fp32+bf16 ---
template <int DH>
__global__ void ln_warp_k(const float* __restrict__ g, const float* __restrict__ beta,
                          int hoff, int T) {
    int w = threadIdx.x >> 5, lane = threadIdx.x & 31;
    int row = blockIdx.x * 8 + w;
    if (row >= T) return;
    const int E = DH / 32;
    float* base = g_H + (size_t)row * HTOT + hoff;
    float v[E];
    float s = 0.f;
    #pragma unroll
    for (int i = 0; i < E; i++) { v[i] = base[lane + i * 32]; s += v[i]; }
    #pragma unroll
    for (int o = 16; o > 0; o >>= 1) s += __shfl_xor_sync(0xffffffffu, s, o);
    float mean = s / (float)DH;
    float q = 0.f;
    #pragma unroll
    for (int i = 0; i < E; i++) { float d = v[i] - mean; q += d * d; }
    #pragma unroll
    for (int o = 16; o > 0; o >>= 1) q += __shfl_xor_sync(0xffffffffu, q, o);
    float r = rsqrtf(q / (float)DH + 1e-12f);
    #pragma unroll
    for (int i = 0; i < E; i++) {
        float y = (v[i] - mean) * r * g[lane + i * 32] + beta[lane + i * 32];
        base[lane + i * 32] = y;
        g_Hb[(size_t)row * HTOT + hoff + lane + i * 32] = __float2bfloat16_rn(y);
    }
}

// ---------------- stats GEMM (bf16 TC, 4-stage cp.async, 2 CTA/SM, dynamic smem) ----------
// logits[i,v] = Hb[i,:].Eb[v,:] + bias[v]; per 128x128 tile emit per-row (max,sumexp,sumlogit)
__global__ void __launch_bounds__(256, 2)
gemm_nt_stats_bf16(const __nv_bfloat16* __restrict__ A, int lda,
                   const float* __restrict__ vbias, int M, int V, int K) {
    extern __shared__ __align__(16) char dyn[];
    // layout: A stages [0, 4*STAGE_B), B stages [4*STAGE_B, 8*STAGE_B),
    //         s_m/s_s/s_l (4*128 floats each), s_bias (128 floats)
    float* s_m   = (float*)(dyn + NSTAGE * STAGE_B * 2);
    float* s_s   = s_m + 4 * 128;
    float* s_l   = s_s + 4 * 128;
    float* s_bias = s_l + 4 * 128;

    int m0 = blockIdx.y * 128, n0 = blockIdx.x * 128;
    int tid = threadIdx.x;
    int warp = tid >> 5, lane = tid & 31;
    int wm = warp >> 2, wn = warp & 3;
    int gr = lane >> 2, gc = lane & 3;

    if (tid < 128) {
        int v = n0 + tid;
        s_bias[tid] = (v < V) ? vbias[v] : 0.0f;
    }

    uint32_t a_base = (uint32_t)__cvta_generic_to_shared(dyn);
    uint32_t b_base = a_base + NSTAGE * STAGE_B;

    float acc[4][4][4];
    #pragma unroll
    for (int mf = 0; mf < 4; mf++)
        #pragma unroll
        for (int nf = 0; nf < 4; nf++)
            #pragma unroll
            for (int q = 0; q < 4; q++) acc[mf][nf][q] = 0.0f;

    int nc = K >> 5;

    // prologue: prefetch first NSTAGE-1 chunks
    #pragma unroll
    for (int s = 0; s < NSTAGE - 1; s++) {
        if (s < nc)
            load_tile_pair(A, lda, M, m0, g_Eb, K, V, n0, s << 5,
                           a_base + s * STAGE_B, b_base + s * STAGE_B, tid);
        CP_COMMIT();
    }

    int a_row_off = wm * 64 + ((lane >> 3) & 1) * 8 + (lane & 7);
    int a_col     = (lane >> 4) * 8;
    int b_row_off = wn * 32 + ((lane >> 4) & 1) * 8 + (lane & 7);
    int b_col     = ((lane >> 3) & 1) * 8;

    for (int c = 0; c < nc; c++) {
        CP_WAIT2();
        __syncthreads();
        int cur = c & (NSTAGE - 1);
        uint32_t abase_s = a_base + cur * STAGE_B;
        uint32_t bbase_s = b_base + cur * STAGE_B;
        #pragma unroll
        for (int ks = 0; ks < 2; ks++) {
            uint32_t af[4][4], bf[2][4];
            #pragma unroll
            for (int mf = 0; mf < 4; mf++)
                ldsm_x4(af[mf], abase_s + ((a_row_off + mf * 16) * BKP + a_col + ks * 16) * 2);
            #pragma unroll
            for (int p = 0; p < 2; p++)
                ldsm_x4(bf[p], bbase_s + ((b_row_off + p * 16) * BKP + b_col + ks * 16) * 2);
            #pragma unroll
            for (int mf = 0; mf < 4; mf++)
                #pragma unroll
                for (int nf = 0; nf < 4; nf++)
                    mma_bf16(acc[mf][nf], af[mf], &bf[nf >> 1][(nf & 1) * 2]);
        }
        // prefetch chunk c + NSTAGE - 1 into the stage freed in the previous iteration
        int nxt = c + NSTAGE - 1;
        if (nxt < nc) {
            int st = nxt & (NSTAGE - 1);
            load_tile_pair(A, lda, M, m0, g_Eb, K, V, n0, nxt << 5,
                           a_base + st * STAGE_B, b_base + st * STAGE_B, tid);
        }
        CP_COMMIT();
    }

    // epilogue: per-row partial stats over this block's 128 columns
    __syncthreads();
    #pragma unroll
    for (int mf = 0; mf < 4; mf++) {
        #pragma unroll
        for (int h = 0; h < 2; h++) {
            int rowb = wm * 64 + mf * 16 + h * 8 + gr;
            float z[8];
            bool valid[8];
            float mloc = -INFINITY;
            #pragma unroll
            for (int nf = 0; nf < 4; nf++) {
                #pragma unroll
                for (int q = 0; q < 2; q++) {
                    int colb = wn * 32 + nf * 8 + gc * 2 + q;
                    int cv = n0 + colb;
                    int j = nf * 2 + q;
                    valid[j] = (cv < V);
                    float zz = acc[mf][nf][h * 2 + q] + s_bias[colb];
                    z[j] = valid[j] ? zz : -INFINITY;
                    if (valid[j]) mloc = fmaxf(mloc, z[j]);
                }
            }
            mloc = fmaxf(mloc, __shfl_xor_sync(0xffffffffu, mloc, 1));
            mloc = fmaxf(mloc, __shfl_xor_sync(0xffffffffu, mloc, 2));
            float sloc = 0.f, slloc = 0.f;
            #pragma unroll
            for (int j = 0; j < 8; j++) {
                if (valid[j]) { sloc += __expf(z[j] - mloc); slloc += z[j]; }
            }
            sloc  += __shfl_xor_sync(0xffffffffu, sloc, 1);
            sloc  += __shfl_xor_sync(0xffffffffu, sloc, 2);
            slloc += __shfl_xor_sync(0xffffffffu, slloc, 1);
            slloc += __shfl_xor_sync(0xffffffffu, slloc, 2);
            if (gc == 0) {
                s_m[wn * 128 + rowb] = mloc;
                s_s[wn * 128 + rowb] = sloc;
                s_l[wn * 128 + rowb] = slloc;
            }
        }
    }
    __syncthreads();
    if (tid < 128) {
        int grow = m0 + tid;
        if (grow < M) {
            float m = -INFINITY, s = 0.f, sl = 0.f;
            #pragma unroll
            for (int w = 0; w < 4; w++) {
                float mp = s_m[w * 128 + tid];
                if (mp > -INFINITY) {
                    float nm = fmaxf(m, mp);
                    s = s * __expf(m - nm) + s_s[w * 128 + tid] * __expf(mp - nm);
                    m = nm;
                }
                sl += s_l[w * 128 + tid];
            }
            size_t off = (size_t)blockIdx.x * M + grow;
            g_pm[off] = m;
            g_ps[off] = s;
            g_psl[off] = sl;
        }
    }
}

// ---------------- per-row merge of partials + target logit + loss accumulation ----------------
__global__ void reduce_softmax_k(const float* __restrict__ vbias,
                                 const int* __restrict__ labels, const int* __restrict__ tsel,
                                 int M, int V, int K, int nVB, int hoff, int accoff) {
    int row = blockIdx.x;
    int tid = threadIdx.x;   // 128 threads
    float m = -INFINITY, s = 0.f, sl = 0.f;
    for (int vb = tid; vb < nVB; vb += 128) {
        size_t off = (size_t)vb * M + row;
        float mp = g_pm[off];
        if (mp > -INFINITY) {
            float nm = fmaxf(m, mp);
            s = s * __expf(m - nm) + g_ps[off] * __expf(mp - nm);
            m = nm;
        }
        sl += g_psl[off];
    }
    __shared__ float sm[128], ss[128], ssl[128], sd[128];
    sm[tid] = m; ss[tid] = s; ssl[tid] = sl;
    __syncthreads();
    for (int o = 64; o > 0; o >>= 1) {
        if (tid < o) {
            float m1 = sm[tid], s1 = ss[tid];
            float m2 = sm[tid + o], s2 = ss[tid + o];
            float nm = fmaxf(m1, m2);
            float ns = 0.f;
            if (m1 > -INFINITY) ns += s1 * __expf(m1 - nm);
            if (m2 > -INFINITY) ns += s2 * __expf(m2 - nm);
            sm[tid] = nm; ss[tid] = ns; ssl[tid] += ssl[tid + o];
        }
        __syncthreads();
    }
    // target logit in bf16 (consistent with logits used for logZ)
    int tgt = labels[tsel[row]];
    float d = 0.f;
    for (int k = tid; k < K; k += 128)
        d += __bfloat162float(g_Hb[(size_t)row * HTOT + hoff + k]) *
             __bfloat162float(g_Eb[(size_t)tgt * K + k]);
    sd[tid] = d; __syncthreads();
    for (int o = 64; o > 0; o >>= 1) { if (tid < o) sd[tid] += sd[tid + o]; __syncthreads(); }
    if (tid == 0) {
        float logZ = sm[0] + logf(ss[0]);
        float tlogit = sd[0] + vbias[tgt];
        float nll = logZ - tlogit;
        float smooth = (float)V * logZ - ssl[0];
        atomicAdd(&g_acc[accoff], nll);
        atomicAdd(&g_acc[accoff + 1], smooth);
    }
}

// ---------------- affix head: z = H[asel]@emb^T + bias, fused BCE-with-logits sum ----------
__global__ void gemm_nt_bce_k(const float* __restrict__ emb, const float* __restrict__ vbias,
                              const float* __restrict__ aprob, const int* __restrict__ tsel,
                              const int* __restrict__ asel, int M, int V, int K, int hoff) {
    __shared__ __align__(16) float As[16][68];
    __shared__ __align__(16) float Bs[16][68];
    __shared__ float red[256];
    int m0 = blockIdx.y * 64, n0 = blockIdx.x * 64;
    int tid = threadIdx.x;
    int tx = tid & 15, ty = tid >> 4;
    int lrow = tid >> 2, lk4 = (tid & 3) * 4;
    float acc[4][4] = {};
    for (int k0 = 0; k0 < K; k0 += 16) {
        float4 av = make_float4(0.f, 0.f, 0.f, 0.f);
        int ar = m0 + lrow;
        if (ar < M) {
            int pr = asel[ar];
            av = *(const float4*)(g_H + (size_t)pr * HTOT + hoff + k0 + lk4);
        }
        As[lk4 + 0][lrow] = av.x; As[lk4 + 1][lrow] = av.y;
        As[lk4 + 2][lrow] = av.z; As[lk4 + 3][lrow] = av.w;
        float4 bv = make_float4(0.f, 0.f, 0.f, 0.f);
        int br = n0 + lrow;
        if (br < V) bv = *(const float4*)(emb + (size_t)br * K + k0 + lk4);
        Bs[lk4 + 0][lrow] = bv.x; Bs[lk4 + 1][lrow] = bv.y;
        Bs[lk4 + 2][lrow] = bv.z; Bs[lk4 + 3][lrow] = bv.w;
        __syncthreads();
        #pragma unroll
        for (int k = 0; k < 16; k++) {
            float4 a4 = *(const float4*)&As[k][ty * 4];
            float4 b4 = *(const float4*)&Bs[k][tx * 4];
            float a_[4] = {a4.x, a4.y, a4.z, a4.w};
            float b_[4] = {b4.x, b4.y, b4.z, b4.w};
            #pragma unroll
            for (int r = 0; r < 4; r++)
                #pragma unroll
                for (int c = 0; c < 4; c++) acc[r][c] += a_[r] * b_[c];
        }
        __syncthreads();
    }
    float lsum = 0.f;
    #pragma unroll
    for (int r = 0; r < 4; r++) {
        int grow = m0 + ty * 4 + r;
        if (grow < M) {
            int trow = tsel[asel[grow]];
            #pragma unroll
            for (int c = 0; c < 4; c++) {
                int v = n0 + tx * 4 + c;
                if (v < V) {
                    float z = acc[r][c] + vbias[v];
                    float t = aprob[(size_t)trow * 360 + v];
                    lsum += fmaxf(z, 0.f) - z * t + log1pf(__expf(-fabsf(z)));
                }
            }
        }
    }
    red[tid] = lsum; __syncthreads();
    for (int o = 128; o > 0; o >>= 1) { if (tid < o) red[tid] += red[tid + o]; __syncthreads(); }
    if (tid == 0) atomicAdd(&g_acc[6], red[0]);
}

// ---------------- finalize: assemble the 7 output scalars ----------------
__global__ void finalize_k(float* __restrict__ out, int T, int Ta) {
    if (threadIdx.x != 0 || blockIdx.x != 0) return;
    const int Vs[3] = {50000, 200, 400};
    for (int h = 0; h < 3; h++) {
        float nll_m = g_acc[2 * h] / (float)T;
        float sm_m  = g_acc[2 * h + 1] / (float)T;
        float eps_i = 0.1f / (float)(Vs[h] - 1);
        out[h] = (1.0f - 0.1f - eps_i) * nll_m + eps_i * sm_m;
        out[4 + h] = nll_m;
    }
    out[3] = g_acc[6] / ((float)Ta * 360.0f);
}

// ---------------- launch ----------------
extern "C" void kernel_launch(void* const* d_in, const int* in_sizes, int n_in,
                              void* d_out, int out_size) {
    const float* hid    = (const float*)d_in[0];
    const float* aprob  = (const float*)d_in[1];
    const int* stems    = (const int*)d_in[2];
    const int* postags  = (const int*)d_in[3];
    const int* morphs   = (const int*)d_in[4];
    const int* hsel     = (const int*)d_in[5];
    const int* tsel     = (const int*)d_in[6];
    const int* asel     = (const int*)d_in[7];
    const float* stem_emb  = (const float*)d_in[8];
    const float* stem_W    = (const float*)d_in[9];
    const float* stem_b    = (const float*)d_in[10];
    const float* stem_g    = (const float*)d_in[11];
    const float* stem_beta = (const float*)d_in[12];
    const float* stem_bias = (const float*)d_in[13];
    const float* pos_emb   = (const float*)d_in[14];
    const float* pos_W     = (const float*)d_in[15];
    const float* pos_b     = (const float*)d_in[16];
    const float* pos_g     = (const float*)d_in[17];
    const float* pos_beta  = (const float*)d_in[18];
    const float* pos_bias  = (const float*)d_in[19];
    const float* morph_emb = (const float*)d_in[20];
    const float* morph_W   = (const float*)d_in[21];
    const float* morph_b   = (const float*)d_in[22];
    const float* morph_g   = (const float*)d_in[23];
    const float* morph_beta= (const float*)d_in[24];
    const float* morph_bias= (const float*)d_in[25];
    const float* aff_emb   = (const float*)d_in[26];
    const float* aff_W     = (const float*)d_in[27];
    const float* aff_b     = (const float*)d_in[28];
    const float* aff_g     = (const float*)d_in[29];
    const float* aff_beta  = (const float*)d_in[30];
    const float* aff_bias  = (const float*)d_in[31];
    float* out = (float*)d_out;

    int T  = in_sizes[5];
    int Ta = in_sizes[7];
    int mT128 = (T + 127) / 128;
    int mTa = (Ta + 63) / 64;
    int lnb = (T + 7) / 8;

    __nv_bfloat16* dEb;
    __nv_bfloat16* dHb;
    cudaGetSymbolAddress((void**)&dEb, g_Eb);
    cudaGetSymbolAddress((void**)&dHb, g_Hb);

    // opt-in to >48KB dynamic smem for the stats kernel (idempotent, not a stream op)
    cudaFuncSetAttribute(gemm_nt_stats_bf16,
                         cudaFuncAttributeMaxDynamicSharedMemorySize, SMEM_STATS);

    zero_acc_k<<<1, 32>>>();
    gather_x_k<<<T, 192>>>(hid, hsel);

    // pack transform weights (transposed bf16) + biases
    cvt_w_k<<<(256 * DMODEL + 255) / 256, 256>>>(stem_W,  stem_b,  256, 0);
    cvt_w_k<<<(128 * DMODEL + 255) / 256, 256>>>(pos_W,   pos_b,   128, 256);
    cvt_w_k<<<(128 * DMODEL + 255) / 256, 256>>>(morph_W, morph_b, 128, 384);
    cvt_w_k<<<(128 * DMODEL + 255) / 256, 256>>>(aff_W,   aff_b,   128, 512);

    // batched transform for all 4 heads
    gemm_tc_gelu<<<dim3(HTOT / 128, mT128), 256>>>(T);

    // per-head LN (warp-per-row)
    ln_warp_k<256><<<lnb, 256>>>(stem_g,  stem_beta,  0,   T);
    ln_warp_k<128><<<lnb, 256>>>(pos_g,   pos_beta,   256, T);
    ln_warp_k<128><<<lnb, 256>>>(morph_g, morph_beta, 384, T);
    ln_warp_k<128><<<lnb, 256>>>(aff_g,   aff_beta,   512, T);

    // ---- stem head: Dh=256, V=50000 ----
    {
        const int Dh = 256, V = 50000, nvb = (V + 127) / 128;
        cvt_bf16_k<<<(V * Dh / 4 + 255) / 256, 256>>>(stem_emb, dEb, V * Dh);
        gemm_nt_stats_bf16<<<dim3(nvb, mT128), 256, SMEM_STATS>>>(dHb + 0, HTOT, stem_bias, T, V, Dh);
        reduce_softmax_k<<<T, 128>>>(stem_bias, stems, tsel, T, V, Dh, nvb, 0, 0);
    }
    // ---- pos head: Dh=128, V=200 ----
    {
        const int Dh = 128, V = 200, nvb = (V + 127) / 128;
        cvt_bf16_k<<<(V * Dh / 4 + 255) / 256, 256>>>(pos_emb, dEb, V * Dh);
        gemm_nt_stats_bf16<<<dim3(nvb, mT128), 256, SMEM_STATS>>>(dHb + 256, HTOT, pos_bias, T, V, Dh);
        reduce_softmax_k<<<T, 128>>>(pos_bias, postags, tsel, T, V, Dh, nvb, 256, 2);
    }
    // ---- morph head: Dh=128, V=400 ----
    {
        const int Dh = 128, V = 400, nvb = (V + 127) / 128;
        cvt_bf16_k<<<(V * Dh / 4 + 255) / 256, 256>>>(morph_emb, dEb, V * Dh);
        gemm_nt_stats_bf16<<<dim3(nvb, mT128), 256, SMEM_STATS>>>(dHb + 384, HTOT, morph_bias, T, V, Dh);
        reduce_softmax_k<<<T, 128>>>(morph_bias, morphs, tsel, T, V, Dh, nvb, 384, 4);
    }
    // ---- affix head: Dh=128, V=360, rows = H[asel[i]], BCE ----
    {
        const int Dh = 128, V = 360;
        gemm_nt_bce_k<<<dim3((V + 63) / 64, mTa), 256>>>(aff_emb, aff_bias, aprob, tsel, asel,
                                                         Ta, V, Dh, 512);
    }

    finalize_k<<<1, 32>>>(out, T, Ta);
}